// round 14
// baseline (speedup 1.0000x reference)
#include <cuda_runtime.h>
#include <cuda_bf16.h>
#include <math.h>
#include <stdint.h>

// Problem constants (fixed for this dataset)
#define N_NODES 4096
#define FEAT    128
#define HID     256
#define KCL     1024
#define NE      131072

// ==================== device scratch ====================
__device__ __align__(16) int   d_cnt_in [N_NODES];
__device__ __align__(16) int   d_cnt_out[N_NODES];
__device__ __align__(16) int   d_selfc  [N_NODES];
__device__ __align__(16) int   d_cur_in [N_NODES];
__device__ __align__(16) int   d_cur_out[N_NODES];
__device__ __align__(16) int   d_off_in [N_NODES];
__device__ __align__(16) int   d_off_out[N_NODES];
__device__ __align__(16) int   d_csc_src[NE];
__device__ __align__(16) int   d_csr_dst[NE];
__device__ __align__(16) float d_dis_sp [N_NODES];
__device__ __align__(16) float d_dis_dn [N_NODES];
__device__ double d_scal[4];   // [0]=ent [1]=cross [2]=sum adj^2 [3]=||G||^2

// fp32 buffers (distinct per split-K GEMM output so they can be pre-zeroed once)
__device__ __align__(16) float g_xwA[N_NODES*HID];   // enc1 out (SK2)
__device__ __align__(16) float g_xwB[N_NODES*HID];   // enc2 out (SK4)
__device__ __align__(16) float g_xwC[N_NODES*HID];   // dec3 out (SK4)
__device__ __align__(16) float g_xwD[N_NODES*HID];   // dec4 out (SK4)
__device__ __align__(16) float g_xwE[N_NODES*FEAT];  // dec5 out (SK4)
__device__ __align__(16) float g_x2 [N_NODES*HID];
__device__ __align__(16) float g_s  [N_NODES*KCL];
__device__ __align__(16) float g_t  [N_NODES*KCL];
__device__ __align__(16) float g_xp [KCL*HID];       // SK16
__device__ __align__(16) float g_adjp[KCL*KCL];      // SK4
__device__ __align__(16) float g_G  [KCL*KCL];       // SK4
__device__ __align__(16) float g_xo [N_NODES*HID];   // SK4

// bf16 split operand buffers
__device__ __align__(16) __nv_bfloat16 g_nhi [N_NODES*FEAT],  g_nlo [N_NODES*FEAT];
__device__ __align__(16) __nv_bfloat16 g_xhi [N_NODES*HID],   g_xlo [N_NODES*HID];
__device__ __align__(16) __nv_bfloat16 g_shi [N_NODES*KCL],   g_slo [N_NODES*KCL];
__device__ __align__(16) __nv_bfloat16 g_sthi[KCL*N_NODES],   g_stlo[KCL*N_NODES];
__device__ __align__(16) __nv_bfloat16 g_tthi[KCL*N_NODES],   g_ttlo[KCL*N_NODES];
__device__ __align__(16) __nv_bfloat16 g_xpthi[HID*KCL],      g_xptlo[HID*KCL];
__device__ __align__(16) __nv_bfloat16 g_apthi[KCL*KCL],      g_aptlo[KCL*KCL];
__device__ __align__(16) __nv_bfloat16 g_mbhi[N_NODES*KCL];
// per-weight transposed bf16 buffers
__device__ __align__(16) __nv_bfloat16 g_w1hi[HID*FEAT], g_w1lo[HID*FEAT];
__device__ __align__(16) __nv_bfloat16 g_w2hi[HID*HID],  g_w2lo[HID*HID];
__device__ __align__(16) __nv_bfloat16 g_wphi[KCL*HID],  g_wplo[KCL*HID];
__device__ __align__(16) __nv_bfloat16 g_w3hi[HID*HID],  g_w3lo[HID*HID];
__device__ __align__(16) __nv_bfloat16 g_w4hi[HID*HID],  g_w4lo[HID*HID];
__device__ __align__(16) __nv_bfloat16 g_w5hi[FEAT*HID], g_w5lo[FEAT*HID];

// ==================== setup kernels ====================
__global__ void init_zero_kernel() {
    int i = blockIdx.x * blockDim.x + threadIdx.x;
    if (i < N_NODES) {
        d_cnt_in[i] = 0; d_cnt_out[i] = 0; d_selfc[i] = 0;
        d_cur_in[i] = 0; d_cur_out[i] = 0;
    }
    if (i < 4) d_scal[i] = 0.0;
}

// one launch: zero every split-K destination buffer
__global__ void zero_all_kernel() {
    size_t stride = (size_t)gridDim.x * blockDim.x * 4;
    size_t base = ((size_t)blockIdx.x * blockDim.x + threadIdx.x) * 4;
#define ZSEG(arr, n) \
    for (size_t i = base; i < (size_t)(n); i += stride) \
        *reinterpret_cast<float4*>((arr) + i) = make_float4(0.f, 0.f, 0.f, 0.f);
    ZSEG(g_xwA, N_NODES * HID)
    ZSEG(g_xwB, N_NODES * HID)
    ZSEG(g_xwC, N_NODES * HID)
    ZSEG(g_xwD, N_NODES * HID)
    ZSEG(g_xwE, N_NODES * FEAT)
    ZSEG(g_xp,  KCL * HID)
    ZSEG(g_adjp, KCL * KCL)
    ZSEG(g_G,   KCL * KCL)
    ZSEG(g_xo,  N_NODES * HID)
#undef ZSEG
}

__global__ void count_kernel(const int* __restrict__ ei, int E) {
    int e = blockIdx.x * blockDim.x + threadIdx.x;
    if (e >= E) return;
    int r = ei[e];
    int c = ei[E + e];
    atomicAdd(&d_cnt_out[r], 1);
    atomicAdd(&d_cnt_in[c], 1);
    if (r == c) atomicAdd(&d_selfc[r], 1);
}

__global__ void scan_kernel() {
    __shared__ int sh[1024];
    int t = threadIdx.x;
    {
        int v = t * 4;
        int a0 = d_cnt_in[v], a1 = d_cnt_in[v+1], a2 = d_cnt_in[v+2], a3 = d_cnt_in[v+3];
        int tot = a0 + a1 + a2 + a3;
        sh[t] = tot; __syncthreads();
        for (int o = 1; o < 1024; o <<= 1) {
            int x = (t >= o) ? sh[t - o] : 0;
            __syncthreads();
            sh[t] += x;
            __syncthreads();
        }
        int excl = sh[t] - tot;
        d_off_in[v]   = excl;
        d_off_in[v+1] = excl + a0;
        d_off_in[v+2] = excl + a0 + a1;
        d_off_in[v+3] = excl + a0 + a1 + a2;
        d_dis_sp[v]   = rsqrtf((float)(a0 + 1));
        d_dis_sp[v+1] = rsqrtf((float)(a1 + 1));
        d_dis_sp[v+2] = rsqrtf((float)(a2 + 1));
        d_dis_sp[v+3] = rsqrtf((float)(a3 + 1));
        __syncthreads();
    }
    {
        int v = t * 4;
        int a0 = d_cnt_out[v], a1 = d_cnt_out[v+1], a2 = d_cnt_out[v+2], a3 = d_cnt_out[v+3];
        int tot = a0 + a1 + a2 + a3;
        sh[t] = tot; __syncthreads();
        for (int o = 1; o < 1024; o <<= 1) {
            int x = (t >= o) ? sh[t - o] : 0;
            __syncthreads();
            sh[t] += x;
            __syncthreads();
        }
        int excl = sh[t] - tot;
        d_off_out[v]   = excl;
        d_off_out[v+1] = excl + a0;
        d_off_out[v+2] = excl + a0 + a1;
        d_off_out[v+3] = excl + a0 + a1 + a2;
        d_dis_dn[v]   = rsqrtf((float)(a0 - d_selfc[v]   + 1));
        d_dis_dn[v+1] = rsqrtf((float)(a1 - d_selfc[v+1] + 1));
        d_dis_dn[v+2] = rsqrtf((float)(a2 - d_selfc[v+2] + 1));
        d_dis_dn[v+3] = rsqrtf((float)(a3 - d_selfc[v+3] + 1));
    }
}

__global__ void fill_kernel(const int* __restrict__ ei, int E) {
    int e = blockIdx.x * blockDim.x + threadIdx.x;
    if (e >= E) return;
    int r = ei[e];
    int c = ei[E + e];
    int p = atomicAdd(&d_cur_in[c], 1);
    d_csc_src[d_off_in[c] + p] = r;
    int q = atomicAdd(&d_cur_out[r], 1);
    d_csr_dst[d_off_out[r] + q] = c;
}

// ==================== split / transpose-split ====================
__global__ void split_kernel(const float* __restrict__ in,
                             __nv_bfloat16* __restrict__ hi,
                             __nv_bfloat16* __restrict__ lo, int n)
{
    int i = (blockIdx.x * blockDim.x + threadIdx.x) * 4;
    if (i >= n) return;
    float4 v = *reinterpret_cast<const float4*>(in + i);
    __nv_bfloat16 h0 = __float2bfloat16(v.x);
    __nv_bfloat16 h1 = __float2bfloat16(v.y);
    __nv_bfloat16 h2 = __float2bfloat16(v.z);
    __nv_bfloat16 h3 = __float2bfloat16(v.w);
    __nv_bfloat162 hh0 = {h0, h1}, hh1 = {h2, h3};
    *reinterpret_cast<__nv_bfloat162*>(hi + i)     = hh0;
    *reinterpret_cast<__nv_bfloat162*>(hi + i + 2) = hh1;
    __nv_bfloat162 ll0 = {__float2bfloat16(v.x - __bfloat162float(h0)),
                          __float2bfloat16(v.y - __bfloat162float(h1))};
    __nv_bfloat162 ll1 = {__float2bfloat16(v.z - __bfloat162float(h2)),
                          __float2bfloat16(v.w - __bfloat162float(h3))};
    *reinterpret_cast<__nv_bfloat162*>(lo + i)     = ll0;
    *reinterpret_cast<__nv_bfloat162*>(lo + i + 2) = ll1;
}

// shared transpose-split body
__device__ __forceinline__ void tsplit_body(const float* in, __nv_bfloat16* hi,
                                            __nv_bfloat16* lo, int R, int C,
                                            int c0, int r0)
{
    __shared__ float tile[32][33];
    int tx = threadIdx.x, ty = threadIdx.y;  // 32 x 8
#pragma unroll
    for (int j = 0; j < 32; j += 8)
        tile[ty + j][tx] = in[(size_t)(r0 + ty + j) * C + c0 + tx];
    __syncthreads();
#pragma unroll
    for (int j = 0; j < 32; j += 8) {
        float x = tile[tx][ty + j];
        __nv_bfloat16 h = __float2bfloat16(x);
        size_t o = (size_t)(c0 + ty + j) * R + r0 + tx;
        hi[o] = h;
        lo[o] = __float2bfloat16(x - __bfloat162float(h));
    }
}

// in fp32 [R,C] -> hi/lo bf16 [C,R]
__global__ void tsplit_kernel(const float* __restrict__ in,
                              __nv_bfloat16* __restrict__ hi,
                              __nv_bfloat16* __restrict__ lo, int R, int C)
{
    tsplit_body(in, hi, lo, R, C, blockIdx.x * 32, blockIdx.y * 32);
}

// batched weight transpose-split: all 6 W matrices in one launch
struct TMat { const float* src; __nv_bfloat16* hi; __nv_bfloat16* lo; int R, C, tile_end; };
struct TBatch { TMat m[6]; };
__global__ void tsplit_batch_kernel(TBatch tb)
{
    int b = blockIdx.x;
    int i = 0;
    while (b >= tb.m[i].tile_end) i++;
    int lt = b - (i == 0 ? 0 : tb.m[i - 1].tile_end);
    int tilesX = tb.m[i].C / 32;
    int c0 = (lt % tilesX) * 32;
    int r0 = (lt / tilesX) * 32;
    tsplit_body(tb.m[i].src, tb.m[i].hi, tb.m[i].lo, tb.m[i].R, tb.m[i].C, c0, r0);
}

// ==================== HMMA common helpers ====================
__device__ __forceinline__ uint32_t smem_u32(const void* p) {
    uint32_t a;
    asm("{ .reg .u64 t; cvta.to.shared.u64 t, %1; cvt.u32.u64 %0, t; }" : "=r"(a) : "l"(p));
    return a;
}
__device__ __forceinline__ void cp_async16(uint32_t saddr, const void* gaddr) {
    asm volatile("cp.async.cg.shared.global [%0], [%1], 16;" :: "r"(saddr), "l"(gaddr));
}
__device__ __forceinline__ void cp_commit() {
    asm volatile("cp.async.commit_group;");
}
__device__ __forceinline__ void ldsm_x4(uint32_t* r, uint32_t addr) {
    asm volatile("ldmatrix.sync.aligned.m8n8.x4.shared.b16 {%0,%1,%2,%3}, [%4];"
        : "=r"(r[0]), "=r"(r[1]), "=r"(r[2]), "=r"(r[3]) : "r"(addr));
}
__device__ __forceinline__ void mma_bf16(float* d, const uint32_t* a, uint32_t b0, uint32_t b1) {
    asm volatile(
        "mma.sync.aligned.m16n8k16.row.col.f32.bf16.bf16.f32 "
        "{%0,%1,%2,%3}, {%4,%5,%6,%7}, {%8,%9}, {%0,%1,%2,%3};"
        : "+f"(d[0]), "+f"(d[1]), "+f"(d[2]), "+f"(d[3])
        : "r"(a[0]), "r"(a[1]), "r"(a[2]), "r"(a[3]), "r"(b0), "r"(b1));
}
__device__ __forceinline__ uint32_t sw128(uint32_t off) {
    return off ^ ((off >> 3) & 0x70);
}

// ==================== 3-term fused split GEMM ====================
#define GEMM3_SMEM_BYTES 131072

__global__ __launch_bounds__(256) void gemm3_mma_kernel(
    const __nv_bfloat16* __restrict__ Ahi, const __nv_bfloat16* __restrict__ Alo,
    const __nv_bfloat16* __restrict__ Bhi, const __nv_bfloat16* __restrict__ Blo,
    float* __restrict__ C, int M, int N, int K)
{
    extern __shared__ char smem[];
    const uint32_t sbase = smem_u32(smem);
    const int tid = threadIdx.x, lane = tid & 31, wid = tid >> 5;
    const int bm = blockIdx.y * 128, bn = blockIdx.x * 128;
    const int wm = (wid >> 1) * 32;
    const int wn = (wid & 1) * 64;

    const int ksz = K / gridDim.z;
    const int k0  = blockIdx.z * ksz;
    const int nch = ksz >> 6;

    float acc[2][8][4];
#pragma unroll
    for (int mi = 0; mi < 2; mi++)
#pragma unroll
        for (int ni = 0; ni < 8; ni++)
#pragma unroll
            for (int q = 0; q < 4; q++) acc[mi][ni][q] = 0.f;

    int lrow[4], lcb[4];
    uint32_t lsw[4];
#pragma unroll
    for (int it = 0; it < 4; it++) {
        int u = tid + it * 256;
        lrow[it] = u >> 3;
        lcb[it]  = u & 7;
        lsw[it]  = sw128((uint32_t)(lrow[it] * 128 + lcb[it] * 16));
    }

    const int a_row = wm + (lane & 15);
    const int a_kof = (lane >> 4) * 8;
    const int b_row = wn + ((lane >> 4) << 3) + (lane & 7);
    const int b_kof = ((lane >> 3) & 1) * 8;

    auto issue = [&](int kc, int buf) {
        uint32_t sbuf = sbase + buf * 65536;
        const __nv_bfloat16* tp[4] = { Ahi, Alo, Bhi, Blo };
#pragma unroll
        for (int tI = 0; tI < 4; tI++) {
            int ro = (tI < 2) ? bm : bn;
            const __nv_bfloat16* P = tp[tI];
            uint32_t sdst = sbuf + tI * 16384;
#pragma unroll
            for (int it = 0; it < 4; it++)
                cp_async16(sdst + lsw[it],
                           P + (size_t)(ro + lrow[it]) * K + k0 + kc * 64 + lcb[it] * 8);
        }
        cp_commit();
    };

    issue(0, 0);
    for (int g = 0; g < nch; g++) {
        if (g + 1 < nch) {
            issue(g + 1, (g + 1) & 1);
            asm volatile("cp.async.wait_group 1;" ::: "memory");
        } else {
            asm volatile("cp.async.wait_group 0;" ::: "memory");
        }
        __syncthreads();
        uint32_t sbuf = sbase + (g & 1) * 65536;
        const uint32_t sAh = sbuf, sAl = sbuf + 16384, sBh = sbuf + 32768, sBl = sbuf + 49152;
#pragma unroll
        for (int kk = 0; kk < 64; kk += 16) {
            uint32_t ah[2][4], al[2][4], bh[4][4], bl[4][4];
#pragma unroll
            for (int mi = 0; mi < 2; mi++) {
                uint32_t off = sw128((uint32_t)((a_row + mi * 16) * 128 + (kk + a_kof) * 2));
                ldsm_x4(ah[mi], sAh + off);
                ldsm_x4(al[mi], sAl + off);
            }
#pragma unroll
            for (int np = 0; np < 4; np++) {
                uint32_t off = sw128((uint32_t)((b_row + np * 16) * 128 + (kk + b_kof) * 2));
                ldsm_x4(bh[np], sBh + off);
                ldsm_x4(bl[np], sBl + off);
            }
#pragma unroll
            for (int mi = 0; mi < 2; mi++)
#pragma unroll
                for (int ni = 0; ni < 8; ni++) {
                    uint32_t b0h = bh[ni >> 1][(ni & 1) * 2], b1h = bh[ni >> 1][(ni & 1) * 2 + 1];
                    uint32_t b0l = bl[ni >> 1][(ni & 1) * 2], b1l = bl[ni >> 1][(ni & 1) * 2 + 1];
                    mma_bf16(acc[mi][ni], ah[mi], b0h, b1h);
                    mma_bf16(acc[mi][ni], al[mi], b0h, b1h);
                    mma_bf16(acc[mi][ni], ah[mi], b0l, b1l);
                }
        }
        __syncthreads();
    }

    const int er = lane >> 2, ec = (lane & 3) * 2;
    if (gridDim.z == 1) {
#pragma unroll
        for (int mi = 0; mi < 2; mi++) {
            int row0 = bm + wm + mi * 16 + er;
#pragma unroll
            for (int ni = 0; ni < 8; ni++) {
                int col = bn + wn + ni * 8 + ec;
                *reinterpret_cast<float2*>(C + (size_t)row0 * N + col) =
                    make_float2(acc[mi][ni][0], acc[mi][ni][1]);
                *reinterpret_cast<float2*>(C + (size_t)(row0 + 8) * N + col) =
                    make_float2(acc[mi][ni][2], acc[mi][ni][3]);
            }
        }
    } else {
#pragma unroll
        for (int mi = 0; mi < 2; mi++) {
            int row0 = bm + wm + mi * 16 + er;
#pragma unroll
            for (int ni = 0; ni < 8; ni++) {
                int col = bn + wn + ni * 8 + ec;
                atomicAdd(C + (size_t)row0 * N + col,       acc[mi][ni][0]);
                atomicAdd(C + (size_t)row0 * N + col + 1,   acc[mi][ni][1]);
                atomicAdd(C + (size_t)(row0 + 8) * N + col,     acc[mi][ni][2]);
                atomicAdd(C + (size_t)(row0 + 8) * N + col + 1, acc[mi][ni][3]);
            }
        }
    }
}

// ==================== 1-term plain bf16 GEMM (positive chains) ====================
#define GEMM1_SMEM_BYTES 65536

// MODE 0: fp32 out (SK via atomics); MODE 1: bf16 out (SK=1);
// MODE 2: paired (z encodes pair<<2|slice; B1/C1 vs B2/C2; SK=4 atomics)
template <int MODE>
__global__ __launch_bounds__(256) void gemm1_mma_kernel(
    const __nv_bfloat16* __restrict__ A,
    const __nv_bfloat16* __restrict__ B1, void* __restrict__ C1v,
    const __nv_bfloat16* __restrict__ B2, void* __restrict__ C2v,
    int M, int N, int K)
{
    extern __shared__ char smem[];
    const uint32_t sbase = smem_u32(smem);
    const int tid = threadIdx.x, lane = tid & 31, wid = tid >> 5;
    const int bm = blockIdx.y * 128, bn = blockIdx.x * 128;
    const int wm = (wid >> 1) * 32;
    const int wn = (wid & 1) * 64;

    const __nv_bfloat16* B;
    void* Cv;
    int ksz, k0, sk;
    if (MODE == 2) {
        int pair = blockIdx.z >> 2, slice = blockIdx.z & 3;
        B = pair ? B2 : B1;
        Cv = pair ? C2v : C1v;
        sk = 4; ksz = K / 4; k0 = slice * ksz;
    } else {
        B = B1; Cv = C1v;
        sk = gridDim.z; ksz = K / sk; k0 = blockIdx.z * ksz;
    }
    const int nch = ksz >> 6;

    float acc[2][8][4];
#pragma unroll
    for (int mi = 0; mi < 2; mi++)
#pragma unroll
        for (int ni = 0; ni < 8; ni++)
#pragma unroll
            for (int q = 0; q < 4; q++) acc[mi][ni][q] = 0.f;

    int lrow[4], lcb[4];
    uint32_t lsw[4];
#pragma unroll
    for (int it = 0; it < 4; it++) {
        int u = tid + it * 256;
        lrow[it] = u >> 3;
        lcb[it]  = u & 7;
        lsw[it]  = sw128((uint32_t)(lrow[it] * 128 + lcb[it] * 16));
    }

    const int a_row = wm + (lane & 15);
    const int a_kof = (lane >> 4) * 8;
    const int b_row = wn + ((lane >> 4) << 3) + (lane & 7);
    const int b_kof = ((lane >> 3) & 1) * 8;

    auto issue = [&](int kc, int buf) {
        uint32_t sbuf = sbase + buf * 32768;
#pragma unroll
        for (int it = 0; it < 4; it++) {
            int col = k0 + kc * 64 + lcb[it] * 8;
            cp_async16(sbuf + lsw[it],         A + (size_t)(bm + lrow[it]) * K + col);
            cp_async16(sbuf + 16384 + lsw[it], B + (size_t)(bn + lrow[it]) * K + col);
        }
        cp_commit();
    };

    issue(0, 0);
    for (int g = 0; g < nch; g++) {
        if (g + 1 < nch) {
            issue(g + 1, (g + 1) & 1);
            asm volatile("cp.async.wait_group 1;" ::: "memory");
        } else {
            asm volatile("cp.async.wait_group 0;" ::: "memory");
        }
        __syncthreads();
        uint32_t sbuf = sbase + (g & 1) * 32768;
        const uint32_t sA = sbuf, sB = sbuf + 16384;
#pragma unroll
        for (int kk = 0; kk < 64; kk += 16) {
            uint32_t af[2][4], bf[4][4];
#pragma unroll
            for (int mi = 0; mi < 2; mi++)
                ldsm_x4(af[mi], sA + sw128((uint32_t)((a_row + mi * 16) * 128 + (kk + a_kof) * 2)));
#pragma unroll
            for (int np = 0; np < 4; np++)
                ldsm_x4(bf[np], sB + sw128((uint32_t)((b_row + np * 16) * 128 + (kk + b_kof) * 2)));
#pragma unroll
            for (int mi = 0; mi < 2; mi++)
#pragma unroll
                for (int ni = 0; ni < 8; ni++)
                    mma_bf16(acc[mi][ni], af[mi],
                             bf[ni >> 1][(ni & 1) * 2], bf[ni >> 1][(ni & 1) * 2 + 1]);
        }
        __syncthreads();
    }

    const int er = lane >> 2, ec = (lane & 3) * 2;
    if (MODE == 1) {
        __nv_bfloat16* C = (__nv_bfloat16*)Cv;
#pragma unroll
        for (int mi = 0; mi < 2; mi++) {
            int row0 = bm + wm + mi * 16 + er;
#pragma unroll
            for (int ni = 0; ni < 8; ni++) {
                int col = bn + wn + ni * 8 + ec;
                __nv_bfloat162 p0 = {__float2bfloat16(acc[mi][ni][0]),
                                     __float2bfloat16(acc[mi][ni][1])};
                __nv_bfloat162 p1 = {__float2bfloat16(acc[mi][ni][2]),
                                     __float2bfloat16(acc[mi][ni][3])};
                *reinterpret_cast<__nv_bfloat162*>(C + (size_t)row0 * N + col)       = p0;
                *reinterpret_cast<__nv_bfloat162*>(C + (size_t)(row0 + 8) * N + col) = p1;
            }
        }
    } else {
        float* C = (float*)Cv;
        if (MODE == 0 && sk == 1) {
#pragma unroll
            for (int mi = 0; mi < 2; mi++) {
                int row0 = bm + wm + mi * 16 + er;
#pragma unroll
                for (int ni = 0; ni < 8; ni++) {
                    int col = bn + wn + ni * 8 + ec;
                    *reinterpret_cast<float2*>(C + (size_t)row0 * N + col) =
                        make_float2(acc[mi][ni][0], acc[mi][ni][1]);
                    *reinterpret_cast<float2*>(C + (size_t)(row0 + 8) * N + col) =
                        make_float2(acc[mi][ni][2], acc[mi][ni][3]);
                }
            }
        } else {
#pragma unroll
            for (int mi = 0; mi < 2; mi++) {
                int row0 = bm + wm + mi * 16 + er;
#pragma unroll
                for (int ni = 0; ni < 8; ni++) {
                    int col = bn + wn + ni * 8 + ec;
                    atomicAdd(C + (size_t)row0 * N + col,       acc[mi][ni][0]);
                    atomicAdd(C + (size_t)row0 * N + col + 1,   acc[mi][ni][1]);
                    atomicAdd(C + (size_t)(row0 + 8) * N + col,     acc[mi][ni][2]);
                    atomicAdd(C + (size_t)(row0 + 8) * N + col + 1, acc[mi][ni][3]);
                }
            }
        }
    }
}

// ==================== sparse aggregation ====================
__global__ void gcn_agg_kernel(const float* __restrict__ xw, const float* __restrict__ bias,
                               float* __restrict__ out, int F, int do_tanh)
{
    int v = blockIdx.x, f = threadIdx.x;
    __shared__ int   sid[256];
    __shared__ float snw[256];
    int nb = d_cnt_in[v], base = d_off_in[v];
    float dv = d_dis_sp[v];
    float acc = 0.f;
    int CH = blockDim.x;
    for (int c0 = 0; c0 < nb; c0 += CH) {
        int m = min(CH, nb - c0);
        __syncthreads();
        if (f < m) {
            int r = d_csc_src[base + c0 + f];
            sid[f] = r;
            snw[f] = d_dis_sp[r];
        }
        __syncthreads();
#pragma unroll 4
        for (int e = 0; e < m; e++)
            acc += snw[e] * xw[(size_t)sid[e] * F + f];
    }
    float o = dv * acc + dv * dv * xw[(size_t)v * F + f] + bias[f];
    out[(size_t)v * F + f] = do_tanh ? tanhf(o) : o;
}

__global__ void gcn_agg_split_kernel(const float* __restrict__ xw, const float* __restrict__ bias,
                                     __nv_bfloat16* __restrict__ hi,
                                     __nv_bfloat16* __restrict__ lo, int F)
{
    int v = blockIdx.x, f = threadIdx.x;
    __shared__ int   sid[256];
    __shared__ float snw[256];
    int nb = d_cnt_in[v], base = d_off_in[v];
    float dv = d_dis_sp[v];
    float acc = 0.f;
    int CH = blockDim.x;
    for (int c0 = 0; c0 < nb; c0 += CH) {
        int m = min(CH, nb - c0);
        __syncthreads();
        if (f < m) {
            int r = d_csc_src[base + c0 + f];
            sid[f] = r;
            snw[f] = d_dis_sp[r];
        }
        __syncthreads();
#pragma unroll 4
        for (int e = 0; e < m; e++)
            acc += snw[e] * xw[(size_t)sid[e] * F + f];
    }
    float o = tanhf(dv * acc + dv * dv * xw[(size_t)v * F + f] + bias[f]);
    __nv_bfloat16 h = __float2bfloat16(o);
    hi[(size_t)v * F + f] = h;
    lo[(size_t)v * F + f] = __float2bfloat16(o - __bfloat162float(h));
}

__global__ void y_agg_split_kernel(const float* __restrict__ x2,
                                   __nv_bfloat16* __restrict__ hi,
                                   __nv_bfloat16* __restrict__ lo)
{
    int v = blockIdx.x, f = threadIdx.x;
    __shared__ int   sid[256];
    __shared__ float snw[256];
    int nb = d_cnt_out[v], base = d_off_out[v];
    float dv = d_dis_dn[v];
    float acc = 0.f;
    for (int c0 = 0; c0 < nb; c0 += 256) {
        int m = min(256, nb - c0);
        __syncthreads();
        if (f < m) {
            int c = d_csr_dst[base + c0 + f];
            sid[f] = c;
            snw[f] = (c == v) ? 0.f : d_dis_dn[c];
        }
        __syncthreads();
#pragma unroll 4
        for (int e = 0; e < m; e++)
            acc += snw[e] * x2[(size_t)sid[e] * HID + f];
    }
    float o = dv * acc + dv * dv * x2[(size_t)v * HID + f];
    __nv_bfloat16 h = __float2bfloat16(o);
    hi[(size_t)v * HID + f] = h;
    lo[(size_t)v * HID + f] = __float2bfloat16(o - __bfloat162float(h));
}

__global__ void t_agg_kernel(const __nv_bfloat16* __restrict__ sh, float* __restrict__ tt)
{
    int v = blockIdx.x, t = threadIdx.x;
    __shared__ int sid[256];
    int nb = d_cnt_out[v], base = d_off_out[v];
    float a0 = 0.f, a1 = 0.f, a2 = 0.f, a3 = 0.f;
    for (int c0 = 0; c0 < nb; c0 += 256) {
        int m = min(256, nb - c0);
        __syncthreads();
        if (t < m) sid[t] = d_csr_dst[base + c0 + t];
        __syncthreads();
#pragma unroll 4
        for (int e = 0; e < m; e++) {
            const __nv_bfloat16* xr = sh + (size_t)sid[e] * KCL;
            __nv_bfloat162 p0 = *reinterpret_cast<const __nv_bfloat162*>(xr + t * 2);
            a0 += __bfloat162float(p0.x);
            a1 += __bfloat162float(p0.y);
            __nv_bfloat162 p1 = *reinterpret_cast<const __nv_bfloat162*>(xr + 512 + t * 2);
            a2 += __bfloat162float(p1.x);
            a3 += __bfloat162float(p1.y);
        }
    }
    tt[(size_t)v * KCL + t * 2]       = a0;
    tt[(size_t)v * KCL + t * 2 + 1]   = a1;
    tt[(size_t)v * KCL + 512 + t * 2]     = a2;
    tt[(size_t)v * KCL + 512 + t * 2 + 1] = a3;
}

__global__ void softmax_ent_kernel(float* __restrict__ s, const float* __restrict__ bp,
                                   __nv_bfloat16* __restrict__ shi,
                                   __nv_bfloat16* __restrict__ slo)
{
    int v = blockIdx.x, t = threadIdx.x;
    float* row = s + (size_t)v * KCL;
    float x0 = row[t]       + bp[t];
    float x1 = row[t + 256] + bp[t + 256];
    float x2 = row[t + 512] + bp[t + 512];
    float x3 = row[t + 768] + bp[t + 768];
    __shared__ float red[256];
    float mx = fmaxf(fmaxf(x0, x1), fmaxf(x2, x3));
    red[t] = mx; __syncthreads();
    for (int o = 128; o > 0; o >>= 1) { if (t < o) red[t] = fmaxf(red[t], red[t + o]); __syncthreads(); }
    float m = red[0]; __syncthreads();
    float e0 = expf(x0 - m), e1 = expf(x1 - m), e2 = expf(x2 - m), e3 = expf(x3 - m);
    red[t] = e0 + e1 + e2 + e3; __syncthreads();
    for (int o = 128; o > 0; o >>= 1) { if (t < o) red[t] += red[t + o]; __syncthreads(); }
    float inv = 1.0f / red[0]; __syncthreads();
    float p0 = e0 * inv, p1 = e1 * inv, p2 = e2 * inv, p3 = e3 * inv;
    row[t] = p0; row[t + 256] = p1; row[t + 512] = p2; row[t + 768] = p3;
    __nv_bfloat16* hrow = shi + (size_t)v * KCL;
    __nv_bfloat16* lrow = slo + (size_t)v * KCL;
    float p[4] = {p0, p1, p2, p3};
#pragma unroll
    for (int q = 0; q < 4; q++) {
        __nv_bfloat16 h = __float2bfloat16(p[q]);
        hrow[t + q * 256] = h;
        lrow[t + q * 256] = __float2bfloat16(p[q] - __bfloat162float(h));
    }
    float ent = -(p0 * logf(p0 + 1e-15f) + p1 * logf(p1 + 1e-15f) +
                  p2 * logf(p2 + 1e-15f) + p3 * logf(p3 + 1e-15f));
    red[t] = ent; __syncthreads();
    for (int o = 128; o > 0; o >>= 1) { if (t < o) red[t] += red[t + o]; __syncthreads(); }
    if (t == 0) atomicAdd(&d_scal[0], (double)red[0]);
}

// merged link-loss reductions: blocks [0,1024) dot<t,s>; [1024,2048) ||G||^2; [2048,6144) dupsq
__global__ void linkloss_kernel(const float* __restrict__ t_arr, const float* __restrict__ s_arr,
                                const float* __restrict__ G_arr)
{
    int b = blockIdx.x;
    if (b < 2048) {
        int slot = (b < 1024) ? 1 : 3;
        const float* a = (b < 1024) ? t_arr : G_arr;
        const float* c = (b < 1024) ? s_arr : G_arr;
        int n = (b < 1024) ? N_NODES * KCL : KCL * KCL;
        int lb = (b < 1024) ? b : b - 1024;
        int i = (lb * 256 + threadIdx.x) * 4;
        float p = 0.f;
        int stride = 1024 * 256 * 4;
        for (; i < n; i += stride) {
            float4 va = *reinterpret_cast<const float4*>(a + i);
            float4 vc = *reinterpret_cast<const float4*>(c + i);
            p += va.x * vc.x + va.y * vc.y + va.z * vc.z + va.w * vc.w;
        }
        __shared__ float red[256];
        red[threadIdx.x] = p; __syncthreads();
        for (int o = 128; o > 0; o >>= 1) {
            if (threadIdx.x < o) red[threadIdx.x] += red[threadIdx.x + o];
            __syncthreads();
        }
        if (threadIdx.x == 0) atomicAdd(&d_scal[slot], (double)red[0]);
    } else {
        int v = b - 2048;
        int t = threadIdx.x;
        int nb = d_cnt_out[v], base = d_off_out[v];
        int tot = 0;
        for (int i = t; i < nb; i += blockDim.x) {
            int ci = d_csr_dst[base + i];
            int c = 0;
            for (int j = 0; j < nb; j++) c += (d_csr_dst[base + j] == ci) ? 1 : 0;
            tot += c;
        }
        __shared__ int redi[256];
        redi[t] = tot; __syncthreads();
        for (int o = 128; o > 0; o >>= 1) {
            if (t < o) redi[t] += redi[t + o];
            __syncthreads();
        }
        if (t == 0 && redi[0] != 0) atomicAdd(&d_scal[2], (double)redi[0]);
    }
}

__global__ void finalize_kernel(float* __restrict__ out_link, float* __restrict__ out_ent)
{
    double v = d_scal[2] - 2.0 * d_scal[1] + d_scal[3];
    if (v < 0.0) v = 0.0;
    *out_link = (float)(0.1 * sqrt(v) / ((double)N_NODES * (double)N_NODES));
    *out_ent  = (float)(0.1 * (d_scal[0] / (double)N_NODES));
}

// ==================== host side ====================
static void gemm3(const __nv_bfloat16* Ah, const __nv_bfloat16* Al,
                  const __nv_bfloat16* Bh, const __nv_bfloat16* Bl,
                  float* C, int M, int N, int K, int SK)
{
    static int attr_done = 0;
    if (!attr_done) {
        cudaFuncSetAttribute(gemm3_mma_kernel, cudaFuncAttributeMaxDynamicSharedMemorySize,
                             GEMM3_SMEM_BYTES);
        attr_done = 1;
    }
    gemm3_mma_kernel<<<dim3(N / 128, M / 128, SK), 256, GEMM3_SMEM_BYTES>>>(Ah, Al, Bh, Bl, C, M, N, K);
}
static void gemm1(const __nv_bfloat16* A, const __nv_bfloat16* B,
                  float* C, int M, int N, int K, int SK)
{
    static int attr_done = 0;
    if (!attr_done) {
        cudaFuncSetAttribute(gemm1_mma_kernel<0>, cudaFuncAttributeMaxDynamicSharedMemorySize,
                             GEMM1_SMEM_BYTES);
        attr_done = 1;
    }
    gemm1_mma_kernel<0><<<dim3(N / 128, M / 128, SK), 256, GEMM1_SMEM_BYTES>>>(
        A, B, C, nullptr, nullptr, M, N, K);
}
static void gemm1_bf16(const __nv_bfloat16* A, const __nv_bfloat16* B,
                       __nv_bfloat16* C, int M, int N, int K)
{
    static int attr_done = 0;
    if (!attr_done) {
        cudaFuncSetAttribute(gemm1_mma_kernel<1>, cudaFuncAttributeMaxDynamicSharedMemorySize,
                             GEMM1_SMEM_BYTES);
        attr_done = 1;
    }
    gemm1_mma_kernel<1><<<dim3(N / 128, M / 128, 1), 256, GEMM1_SMEM_BYTES>>>(
        A, B, C, nullptr, nullptr, M, N, K);
}
static void gemm1_pair(const __nv_bfloat16* A,
                       const __nv_bfloat16* B1, float* C1,
                       const __nv_bfloat16* B2, float* C2, int M, int N, int K)
{
    static int attr_done = 0;
    if (!attr_done) {
        cudaFuncSetAttribute(gemm1_mma_kernel<2>, cudaFuncAttributeMaxDynamicSharedMemorySize,
                             GEMM1_SMEM_BYTES);
        attr_done = 1;
    }
    gemm1_mma_kernel<2><<<dim3(N / 128, M / 128, 8), 256, GEMM1_SMEM_BYTES>>>(
        A, B1, C1, B2, C2, M, N, K);
}
static void split_f(const float* in, __nv_bfloat16* hi, __nv_bfloat16* lo, int n)
{
    split_kernel<<<(n / 4 + 255) / 256, 256>>>(in, hi, lo, n);
}
static void tsplit_f(const float* in, __nv_bfloat16* hi, __nv_bfloat16* lo, int R, int C)
{
    tsplit_kernel<<<dim3(C / 32, R / 32), dim3(32, 8)>>>(in, hi, lo, R, C);
}

extern "C" void kernel_launch(void* const* d_in, const int* in_sizes, int n_in,
                              void* d_out, int out_size)
{
    const float* nodes = (const float*)d_in[0];
    const int*   ei    = (const int*)d_in[1];
    const float* W1 = (const float*)d_in[3];  const float* b1 = (const float*)d_in[4];
    const float* W2 = (const float*)d_in[5];  const float* b2 = (const float*)d_in[6];
    const float* Wp = (const float*)d_in[7];  const float* bp = (const float*)d_in[8];
    const float* W3 = (const float*)d_in[9];  const float* b3 = (const float*)d_in[10];
    const float* W4 = (const float*)d_in[11]; const float* b4 = (const float*)d_in[12];
    const float* W5 = (const float*)d_in[13]; const float* b5 = (const float*)d_in[14];
    int E = in_sizes[1] / 2;

    float* out      = (float*)d_out;
    float* out_x    = out;
    float* out_adj  = out + (size_t)N_NODES * FEAT;
    float* out_link = out + (size_t)N_NODES * FEAT + (size_t)N_NODES * N_NODES;
    float* out_ent  = out_link + 1;

    float *xwA,*xwB,*xwC,*xwD,*xwE,*x2,*s,*t,*xp,*adjp,*G,*xo;
    cudaGetSymbolAddress((void**)&xwA,  g_xwA);
    cudaGetSymbolAddress((void**)&xwB,  g_xwB);
    cudaGetSymbolAddress((void**)&xwC,  g_xwC);
    cudaGetSymbolAddress((void**)&xwD,  g_xwD);
    cudaGetSymbolAddress((void**)&xwE,  g_xwE);
    cudaGetSymbolAddress((void**)&x2,   g_x2);
    cudaGetSymbolAddress((void**)&s,    g_s);
    cudaGetSymbolAddress((void**)&t,    g_t);
    cudaGetSymbolAddress((void**)&xp,   g_xp);
    cudaGetSymbolAddress((void**)&adjp, g_adjp);
    cudaGetSymbolAddress((void**)&G,    g_G);
    cudaGetSymbolAddress((void**)&xo,   g_xo);

    __nv_bfloat16 *nhi,*nlo,*xhi,*xlo,*shi,*slo,*sthi,*stlo,*tthi,*ttlo;
    __nv_bfloat16 *xpthi,*xptlo,*apthi,*aptlo,*mbhi;
    __nv_bfloat16 *w1hi,*w1lo,*w2hi,*w2lo,*wphi,*wplo,*w3hi,*w3lo,*w4hi,*w4lo,*w5hi,*w5lo;
    cudaGetSymbolAddress((void**)&nhi,  g_nhi);  cudaGetSymbolAddress((void**)&nlo,  g_nlo);
    cudaGetSymbolAddress((void**)&xhi,  g_xhi);  cudaGetSymbolAddress((void**)&xlo,  g_xlo);
    cudaGetSymbolAddress((void**)&shi,  g_shi);  cudaGetSymbolAddress((void**)&slo,  g_slo);
    cudaGetSymbolAddress((void**)&sthi, g_sthi); cudaGetSymbolAddress((void**)&stlo, g_stlo);
    cudaGetSymbolAddress((void**)&tthi, g_tthi); cudaGetSymbolAddress((void**)&ttlo, g_ttlo);
    cudaGetSymbolAddress((void**)&xpthi,g_xpthi);cudaGetSymbolAddress((void**)&xptlo,g_xptlo);
    cudaGetSymbolAddress((void**)&apthi,g_apthi);cudaGetSymbolAddress((void**)&aptlo,g_aptlo);
    cudaGetSymbolAddress((void**)&mbhi, g_mbhi);
    cudaGetSymbolAddress((void**)&w1hi, g_w1hi); cudaGetSymbolAddress((void**)&w1lo, g_w1lo);
    cudaGetSymbolAddress((void**)&w2hi, g_w2hi); cudaGetSymbolAddress((void**)&w2lo, g_w2lo);
    cudaGetSymbolAddress((void**)&wphi, g_wphi); cudaGetSymbolAddress((void**)&wplo, g_wplo);
    cudaGetSymbolAddress((void**)&w3hi, g_w3hi); cudaGetSymbolAddress((void**)&w3lo, g_w3lo);
    cudaGetSymbolAddress((void**)&w4hi, g_w4hi); cudaGetSymbolAddress((void**)&w4lo, g_w4lo);
    cudaGetSymbolAddress((void**)&w5hi, g_w5hi); cudaGetSymbolAddress((void**)&w5lo, g_w5lo);

    // ---- batched weight transpose + buffer zero + graph prep ----
    TBatch tb;
    int acc_t = 0;
    auto set_m = [&](int i, const float* src, __nv_bfloat16* hi, __nv_bfloat16* lo, int R, int C) {
        acc_t += (C / 32) * (R / 32);
        tb.m[i] = TMat{src, hi, lo, R, C, acc_t};
    };
    set_m(0, W1, w1hi, w1lo, FEAT, HID);
    set_m(1, W2, w2hi, w2lo, HID, HID);
    set_m(2, Wp, wphi, wplo, HID, KCL);
    set_m(3, W3, w3hi, w3lo, HID, HID);
    set_m(4, W4, w4hi, w4lo, HID, HID);
    set_m(5, W5, w5hi, w5lo, HID, FEAT);
    tsplit_batch_kernel<<<acc_t, dim3(32, 8)>>>(tb);
    zero_all_kernel<<<1024, 256>>>();
    init_zero_kernel<<<(N_NODES + 255) / 256, 256>>>();
    count_kernel<<<(E + 255) / 256, 256>>>(ei, E);
    scan_kernel<<<1, 1024>>>();
    fill_kernel<<<(E + 255) / 256, 256>>>(ei, E);
    split_f(nodes, nhi, nlo, N_NODES * FEAT);

    // ---- encoder ----
    gemm3(nhi, nlo, w1hi, w1lo, xwA, N_NODES, HID, FEAT, 2);
    gcn_agg_split_kernel<<<N_NODES, HID>>>(xwA, b1, xhi, xlo, HID);
    gemm3(xhi, xlo, w2hi, w2lo, xwB, N_NODES, HID, HID, 4);
    gcn_agg_kernel<<<N_NODES, HID>>>(xwB, b2, x2, HID, 1);

    // ---- assignment ----
    y_agg_split_kernel<<<N_NODES, HID>>>(x2, xhi, xlo);
    gemm3(xhi, xlo, wphi, wplo, s, N_NODES, KCL, HID, 1);
    softmax_ent_kernel<<<N_NODES, 256>>>(s, bp, shi, slo);

    // ---- pooling ----
    tsplit_f(s, sthi, stlo, N_NODES, KCL);
    tsplit_f(x2, xhi, xlo, N_NODES, HID);
    gemm3(sthi, stlo, xhi, xlo, xp, KCL, HID, N_NODES, 16);
    t_agg_kernel<<<N_NODES, 256>>>(shi, t);
    tsplit_f(t, tthi, ttlo, N_NODES, KCL);
    gemm1_pair(sthi, tthi, adjp, sthi, G, KCL, KCL, N_NODES);  // adjp & G in one launch

    // link-loss (merged): cross=<t,s>, ||G||^2, sum adj^2
    linkloss_kernel<<<6144, 256>>>(t, s, G);

    // ---- un-pool ----
    tsplit_f(xp, xpthi, xptlo, KCL, HID);
    gemm3(shi, slo, xpthi, xptlo, xo, N_NODES, HID, KCL, 4);
    tsplit_f(adjp, apthi, aptlo, KCL, KCL);
    gemm1_bf16(shi, apthi, mbhi, N_NODES, KCL, KCL);
    gemm1(mbhi, shi, out_adj, N_NODES, N_NODES, KCL, 1);

    // ---- decoder ----
    split_f(xo, xhi, xlo, N_NODES * HID);
    gemm3(xhi, xlo, w3hi, w3lo, xwC, N_NODES, HID, HID, 4);
    gcn_agg_split_kernel<<<N_NODES, HID>>>(xwC, b3, xhi, xlo, HID);
    gemm3(xhi, xlo, w4hi, w4lo, xwD, N_NODES, HID, HID, 4);
    gcn_agg_split_kernel<<<N_NODES, HID>>>(xwD, b4, xhi, xlo, HID);
    gemm3(xhi, xlo, w5hi, w5lo, xwE, N_NODES, FEAT, HID, 4);
    gcn_agg_kernel<<<N_NODES, FEAT>>>(xwE, b5, out_x, FEAT, 0);

    // scalars
    finalize_kernel<<<1, 1>>>(out_link, out_ent);
}

// round 15
// speedup vs baseline: 1.0918x; 1.0918x over previous
#include <cuda_runtime.h>
#include <cuda_bf16.h>
#include <math.h>
#include <stdint.h>

// Problem constants (fixed for this dataset)
#define N_NODES 4096
#define FEAT    128
#define HID     256
#define KCL     1024
#define NE      131072

// ==================== device scratch ====================
__device__ __align__(16) int   d_cnt_in [N_NODES];
__device__ __align__(16) int   d_cnt_out[N_NODES];
__device__ __align__(16) int   d_selfc  [N_NODES];
__device__ __align__(16) int   d_cur_in [N_NODES];
__device__ __align__(16) int   d_cur_out[N_NODES];
__device__ __align__(16) int   d_off_in [N_NODES];
__device__ __align__(16) int   d_off_out[N_NODES];
__device__ __align__(16) int   d_csc_src[NE];
__device__ __align__(16) int   d_csr_dst[NE];
__device__ __align__(16) float d_dis_sp [N_NODES];
__device__ __align__(16) float d_dis_dn [N_NODES];
__device__ double d_scal[4];   // [0]=ent [1]=cross [2]=sum adj^2 [3]=||G||^2

// fp32 buffers (distinct per split-K GEMM output so they can be pre-zeroed once)
__device__ __align__(16) float g_xwA[N_NODES*HID];   // enc1 out (SK2)
__device__ __align__(16) float g_xwB[N_NODES*HID];   // enc2 out (SK4)
__device__ __align__(16) float g_xwC[N_NODES*HID];   // dec3 out (SK4)
__device__ __align__(16) float g_xwD[N_NODES*HID];   // dec4 out (SK4)
__device__ __align__(16) float g_xwE[N_NODES*FEAT];  // dec5 out (SK4)
__device__ __align__(16) float g_x2 [N_NODES*HID];
__device__ __align__(16) float g_s  [N_NODES*KCL];
__device__ __align__(16) float g_t  [N_NODES*KCL];
__device__ __align__(16) float g_xp [KCL*HID];       // SK16
__device__ __align__(16) float g_adjp[KCL*KCL];      // SK4
__device__ __align__(16) float g_G  [KCL*KCL];       // SK4
__device__ __align__(16) float g_xo [N_NODES*HID];   // SK4

// bf16 split operand buffers
__device__ __align__(16) __nv_bfloat16 g_nhi [N_NODES*FEAT],  g_nlo [N_NODES*FEAT];
__device__ __align__(16) __nv_bfloat16 g_xhi [N_NODES*HID],   g_xlo [N_NODES*HID];
__device__ __align__(16) __nv_bfloat16 g_shi [N_NODES*KCL],   g_slo [N_NODES*KCL];
__device__ __align__(16) __nv_bfloat16 g_sthi[KCL*N_NODES],   g_stlo[KCL*N_NODES];
__device__ __align__(16) __nv_bfloat16 g_x2thi[HID*N_NODES],  g_x2tlo[HID*N_NODES];
__device__ __align__(16) __nv_bfloat16 g_tthi[KCL*N_NODES],   g_ttlo[KCL*N_NODES];
__device__ __align__(16) __nv_bfloat16 g_xpthi[HID*KCL],      g_xptlo[HID*KCL];
__device__ __align__(16) __nv_bfloat16 g_apthi[KCL*KCL],      g_aptlo[KCL*KCL];
__device__ __align__(16) __nv_bfloat16 g_mbhi[N_NODES*KCL];
// per-weight transposed bf16 buffers
__device__ __align__(16) __nv_bfloat16 g_w1hi[HID*FEAT], g_w1lo[HID*FEAT];
__device__ __align__(16) __nv_bfloat16 g_w2hi[HID*HID],  g_w2lo[HID*HID];
__device__ __align__(16) __nv_bfloat16 g_wphi[KCL*HID],  g_wplo[KCL*HID];
__device__ __align__(16) __nv_bfloat16 g_w3hi[HID*HID],  g_w3lo[HID*HID];
__device__ __align__(16) __nv_bfloat16 g_w4hi[HID*HID],  g_w4lo[HID*HID];
__device__ __align__(16) __nv_bfloat16 g_w5hi[FEAT*HID], g_w5lo[FEAT*HID];

// ==================== setup kernels ====================
__global__ void init_zero_kernel() {
    int i = blockIdx.x * blockDim.x + threadIdx.x;
    if (i < N_NODES) {
        d_cnt_in[i] = 0; d_cnt_out[i] = 0; d_selfc[i] = 0;
        d_cur_in[i] = 0; d_cur_out[i] = 0;
    }
    if (i < 4) d_scal[i] = 0.0;
}

// one launch: zero every split-K destination buffer
__global__ void zero_all_kernel() {
    size_t stride = (size_t)gridDim.x * blockDim.x * 4;
    size_t base = ((size_t)blockIdx.x * blockDim.x + threadIdx.x) * 4;
#define ZSEG(arr, n) \
    for (size_t i = base; i < (size_t)(n); i += stride) \
        *reinterpret_cast<float4*>((arr) + i) = make_float4(0.f, 0.f, 0.f, 0.f);
    ZSEG(g_xwA, N_NODES * HID)
    ZSEG(g_xwB, N_NODES * HID)
    ZSEG(g_xwC, N_NODES * HID)
    ZSEG(g_xwD, N_NODES * HID)
    ZSEG(g_xwE, N_NODES * FEAT)
    ZSEG(g_xp,  KCL * HID)
    ZSEG(g_adjp, KCL * KCL)
    ZSEG(g_G,   KCL * KCL)
    ZSEG(g_xo,  N_NODES * HID)
#undef ZSEG
}

__global__ void count_kernel(const int* __restrict__ ei, int E) {
    int e = blockIdx.x * blockDim.x + threadIdx.x;
    if (e >= E) return;
    int r = ei[e];
    int c = ei[E + e];
    atomicAdd(&d_cnt_out[r], 1);
    atomicAdd(&d_cnt_in[c], 1);
    if (r == c) atomicAdd(&d_selfc[r], 1);
}

__global__ void scan_kernel() {
    __shared__ int sh[1024];
    int t = threadIdx.x;
    {
        int v = t * 4;
        int a0 = d_cnt_in[v], a1 = d_cnt_in[v+1], a2 = d_cnt_in[v+2], a3 = d_cnt_in[v+3];
        int tot = a0 + a1 + a2 + a3;
        sh[t] = tot; __syncthreads();
        for (int o = 1; o < 1024; o <<= 1) {
            int x = (t >= o) ? sh[t - o] : 0;
            __syncthreads();
            sh[t] += x;
            __syncthreads();
        }
        int excl = sh[t] - tot;
        d_off_in[v]   = excl;
        d_off_in[v+1] = excl + a0;
        d_off_in[v+2] = excl + a0 + a1;
        d_off_in[v+3] = excl + a0 + a1 + a2;
        d_dis_sp[v]   = rsqrtf((float)(a0 + 1));
        d_dis_sp[v+1] = rsqrtf((float)(a1 + 1));
        d_dis_sp[v+2] = rsqrtf((float)(a2 + 1));
        d_dis_sp[v+3] = rsqrtf((float)(a3 + 1));
        __syncthreads();
    }
    {
        int v = t * 4;
        int a0 = d_cnt_out[v], a1 = d_cnt_out[v+1], a2 = d_cnt_out[v+2], a3 = d_cnt_out[v+3];
        int tot = a0 + a1 + a2 + a3;
        sh[t] = tot; __syncthreads();
        for (int o = 1; o < 1024; o <<= 1) {
            int x = (t >= o) ? sh[t - o] : 0;
            __syncthreads();
            sh[t] += x;
            __syncthreads();
        }
        int excl = sh[t] - tot;
        d_off_out[v]   = excl;
        d_off_out[v+1] = excl + a0;
        d_off_out[v+2] = excl + a0 + a1;
        d_off_out[v+3] = excl + a0 + a1 + a2;
        d_dis_dn[v]   = rsqrtf((float)(a0 - d_selfc[v]   + 1));
        d_dis_dn[v+1] = rsqrtf((float)(a1 - d_selfc[v+1] + 1));
        d_dis_dn[v+2] = rsqrtf((float)(a2 - d_selfc[v+2] + 1));
        d_dis_dn[v+3] = rsqrtf((float)(a3 - d_selfc[v+3] + 1));
    }
}

__global__ void fill_kernel(const int* __restrict__ ei, int E) {
    int e = blockIdx.x * blockDim.x + threadIdx.x;
    if (e >= E) return;
    int r = ei[e];
    int c = ei[E + e];
    int p = atomicAdd(&d_cur_in[c], 1);
    d_csc_src[d_off_in[c] + p] = r;
    int q = atomicAdd(&d_cur_out[r], 1);
    d_csr_dst[d_off_out[r] + q] = c;
}

// ==================== split / transpose-split ====================
__global__ void split_kernel(const float* __restrict__ in,
                             __nv_bfloat16* __restrict__ hi,
                             __nv_bfloat16* __restrict__ lo, int n)
{
    int i = (blockIdx.x * blockDim.x + threadIdx.x) * 4;
    if (i >= n) return;
    float4 v = *reinterpret_cast<const float4*>(in + i);
    __nv_bfloat16 h0 = __float2bfloat16(v.x);
    __nv_bfloat16 h1 = __float2bfloat16(v.y);
    __nv_bfloat16 h2 = __float2bfloat16(v.z);
    __nv_bfloat16 h3 = __float2bfloat16(v.w);
    __nv_bfloat162 hh0 = {h0, h1}, hh1 = {h2, h3};
    *reinterpret_cast<__nv_bfloat162*>(hi + i)     = hh0;
    *reinterpret_cast<__nv_bfloat162*>(hi + i + 2) = hh1;
    __nv_bfloat162 ll0 = {__float2bfloat16(v.x - __bfloat162float(h0)),
                          __float2bfloat16(v.y - __bfloat162float(h1))};
    __nv_bfloat162 ll1 = {__float2bfloat16(v.z - __bfloat162float(h2)),
                          __float2bfloat16(v.w - __bfloat162float(h3))};
    *reinterpret_cast<__nv_bfloat162*>(lo + i)     = ll0;
    *reinterpret_cast<__nv_bfloat162*>(lo + i + 2) = ll1;
}

// shared transpose-split body
__device__ __forceinline__ void tsplit_body(const float* in, __nv_bfloat16* hi,
                                            __nv_bfloat16* lo, int R, int C,
                                            int c0, int r0)
{
    __shared__ float tile[32][33];
    int tx = threadIdx.x, ty = threadIdx.y;  // 32 x 8
#pragma unroll
    for (int j = 0; j < 32; j += 8)
        tile[ty + j][tx] = in[(size_t)(r0 + ty + j) * C + c0 + tx];
    __syncthreads();
#pragma unroll
    for (int j = 0; j < 32; j += 8) {
        float x = tile[tx][ty + j];
        __nv_bfloat16 h = __float2bfloat16(x);
        size_t o = (size_t)(c0 + ty + j) * R + r0 + tx;
        hi[o] = h;
        lo[o] = __float2bfloat16(x - __bfloat162float(h));
    }
}

__global__ void tsplit_kernel(const float* __restrict__ in,
                              __nv_bfloat16* __restrict__ hi,
                              __nv_bfloat16* __restrict__ lo, int R, int C)
{
    tsplit_body(in, hi, lo, R, C, blockIdx.x * 32, blockIdx.y * 32);
}

// batched weight transpose-split: all 6 W matrices in one launch
struct TMat { const float* src; __nv_bfloat16* hi; __nv_bfloat16* lo; int R, C, tile_end; };
struct TBatch { TMat m[6]; };
__global__ void tsplit_batch_kernel(TBatch tb)
{
    int b = blockIdx.x;
    int i = 0;
    while (b >= tb.m[i].tile_end) i++;
    int lt = b - (i == 0 ? 0 : tb.m[i - 1].tile_end);
    int tilesX = tb.m[i].C / 32;
    int c0 = (lt % tilesX) * 32;
    int r0 = (lt / tilesX) * 32;
    tsplit_body(tb.m[i].src, tb.m[i].hi, tb.m[i].lo, tb.m[i].R, tb.m[i].C, c0, r0);
}

// ==================== HMMA common helpers ====================
__device__ __forceinline__ uint32_t smem_u32(const void* p) {
    uint32_t a;
    asm("{ .reg .u64 t; cvta.to.shared.u64 t, %1; cvt.u32.u64 %0, t; }" : "=r"(a) : "l"(p));
    return a;
}
__device__ __forceinline__ void cp_async16(uint32_t saddr, const void* gaddr) {
    asm volatile("cp.async.cg.shared.global [%0], [%1], 16;" :: "r"(saddr), "l"(gaddr));
}
__device__ __forceinline__ void cp_commit() {
    asm volatile("cp.async.commit_group;");
}
__device__ __forceinline__ void ldsm_x4(uint32_t* r, uint32_t addr) {
    asm volatile("ldmatrix.sync.aligned.m8n8.x4.shared.b16 {%0,%1,%2,%3}, [%4];"
        : "=r"(r[0]), "=r"(r[1]), "=r"(r[2]), "=r"(r[3]) : "r"(addr));
}
__device__ __forceinline__ void mma_bf16(float* d, const uint32_t* a, uint32_t b0, uint32_t b1) {
    asm volatile(
        "mma.sync.aligned.m16n8k16.row.col.f32.bf16.bf16.f32 "
        "{%0,%1,%2,%3}, {%4,%5,%6,%7}, {%8,%9}, {%0,%1,%2,%3};"
        : "+f"(d[0]), "+f"(d[1]), "+f"(d[2]), "+f"(d[3])
        : "r"(a[0]), "r"(a[1]), "r"(a[2]), "r"(a[3]), "r"(b0), "r"(b1));
}
__device__ __forceinline__ uint32_t sw128(uint32_t off) {
    return off ^ ((off >> 3) & 0x70);
}

// ==================== 3-term fused split GEMM ====================
#define GEMM3_SMEM_BYTES 131072

__global__ __launch_bounds__(256) void gemm3_mma_kernel(
    const __nv_bfloat16* __restrict__ Ahi, const __nv_bfloat16* __restrict__ Alo,
    const __nv_bfloat16* __restrict__ Bhi, const __nv_bfloat16* __restrict__ Blo,
    float* __restrict__ C, int M, int N, int K)
{
    extern __shared__ char smem[];
    const uint32_t sbase = smem_u32(smem);
    const int tid = threadIdx.x, lane = tid & 31, wid = tid >> 5;
    const int bm = blockIdx.y * 128, bn = blockIdx.x * 128;
    const int wm = (wid >> 1) * 32;
    const int wn = (wid & 1) * 64;

    const int ksz = K / gridDim.z;
    const int k0  = blockIdx.z * ksz;
    const int nch = ksz >> 6;

    float acc[2][8][4];
#pragma unroll
    for (int mi = 0; mi < 2; mi++)
#pragma unroll
        for (int ni = 0; ni < 8; ni++)
#pragma unroll
            for (int q = 0; q < 4; q++) acc[mi][ni][q] = 0.f;

    int lrow[4], lcb[4];
    uint32_t lsw[4];
#pragma unroll
    for (int it = 0; it < 4; it++) {
        int u = tid + it * 256;
        lrow[it] = u >> 3;
        lcb[it]  = u & 7;
        lsw[it]  = sw128((uint32_t)(lrow[it] * 128 + lcb[it] * 16));
    }

    const int a_row = wm + (lane & 15);
    const int a_kof = (lane >> 4) * 8;
    const int b_row = wn + ((lane >> 4) << 3) + (lane & 7);
    const int b_kof = ((lane >> 3) & 1) * 8;

    auto issue = [&](int kc, int buf) {
        uint32_t sbuf = sbase + buf * 65536;
        const __nv_bfloat16* tp[4] = { Ahi, Alo, Bhi, Blo };
#pragma unroll
        for (int tI = 0; tI < 4; tI++) {
            int ro = (tI < 2) ? bm : bn;
            const __nv_bfloat16* P = tp[tI];
            uint32_t sdst = sbuf + tI * 16384;
#pragma unroll
            for (int it = 0; it < 4; it++)
                cp_async16(sdst + lsw[it],
                           P + (size_t)(ro + lrow[it]) * K + k0 + kc * 64 + lcb[it] * 8);
        }
        cp_commit();
    };

    issue(0, 0);
    for (int g = 0; g < nch; g++) {
        if (g + 1 < nch) {
            issue(g + 1, (g + 1) & 1);
            asm volatile("cp.async.wait_group 1;" ::: "memory");
        } else {
            asm volatile("cp.async.wait_group 0;" ::: "memory");
        }
        __syncthreads();
        uint32_t sbuf = sbase + (g & 1) * 65536;
        const uint32_t sAh = sbuf, sAl = sbuf + 16384, sBh = sbuf + 32768, sBl = sbuf + 49152;
#pragma unroll
        for (int kk = 0; kk < 64; kk += 16) {
            uint32_t ah[2][4], al[2][4], bh[4][4], bl[4][4];
#pragma unroll
            for (int mi = 0; mi < 2; mi++) {
                uint32_t off = sw128((uint32_t)((a_row + mi * 16) * 128 + (kk + a_kof) * 2));
                ldsm_x4(ah[mi], sAh + off);
                ldsm_x4(al[mi], sAl + off);
            }
#pragma unroll
            for (int np = 0; np < 4; np++) {
                uint32_t off = sw128((uint32_t)((b_row + np * 16) * 128 + (kk + b_kof) * 2));
                ldsm_x4(bh[np], sBh + off);
                ldsm_x4(bl[np], sBl + off);
            }
#pragma unroll
            for (int mi = 0; mi < 2; mi++)
#pragma unroll
                for (int ni = 0; ni < 8; ni++) {
                    uint32_t b0h = bh[ni >> 1][(ni & 1) * 2], b1h = bh[ni >> 1][(ni & 1) * 2 + 1];
                    uint32_t b0l = bl[ni >> 1][(ni & 1) * 2], b1l = bl[ni >> 1][(ni & 1) * 2 + 1];
                    mma_bf16(acc[mi][ni], ah[mi], b0h, b1h);
                    mma_bf16(acc[mi][ni], al[mi], b0h, b1h);
                    mma_bf16(acc[mi][ni], ah[mi], b0l, b1l);
                }
        }
        __syncthreads();
    }

    const int er = lane >> 2, ec = (lane & 3) * 2;
    if (gridDim.z == 1) {
#pragma unroll
        for (int mi = 0; mi < 2; mi++) {
            int row0 = bm + wm + mi * 16 + er;
#pragma unroll
            for (int ni = 0; ni < 8; ni++) {
                int col = bn + wn + ni * 8 + ec;
                *reinterpret_cast<float2*>(C + (size_t)row0 * N + col) =
                    make_float2(acc[mi][ni][0], acc[mi][ni][1]);
                *reinterpret_cast<float2*>(C + (size_t)(row0 + 8) * N + col) =
                    make_float2(acc[mi][ni][2], acc[mi][ni][3]);
            }
        }
    } else {
#pragma unroll
        for (int mi = 0; mi < 2; mi++) {
            int row0 = bm + wm + mi * 16 + er;
#pragma unroll
            for (int ni = 0; ni < 8; ni++) {
                int col = bn + wn + ni * 8 + ec;
                atomicAdd(C + (size_t)row0 * N + col,       acc[mi][ni][0]);
                atomicAdd(C + (size_t)row0 * N + col + 1,   acc[mi][ni][1]);
                atomicAdd(C + (size_t)(row0 + 8) * N + col,     acc[mi][ni][2]);
                atomicAdd(C + (size_t)(row0 + 8) * N + col + 1, acc[mi][ni][3]);
            }
        }
    }
}

// ==================== 1-term plain bf16 GEMM (positive chains) ====================
#define GEMM1_SMEM_BYTES 65536

// MODE 0: fp32 out (SK via atomics); MODE 1: bf16 out (SK=1);
// MODE 2: paired (z encodes pair<<2|slice)
template <int MODE>
__global__ __launch_bounds__(256) void gemm1_mma_kernel(
    const __nv_bfloat16* __restrict__ A,
    const __nv_bfloat16* __restrict__ B1, void* __restrict__ C1v,
    const __nv_bfloat16* __restrict__ B2, void* __restrict__ C2v,
    int M, int N, int K)
{
    extern __shared__ char smem[];
    const uint32_t sbase = smem_u32(smem);
    const int tid = threadIdx.x, lane = tid & 31, wid = tid >> 5;
    const int bm = blockIdx.y * 128, bn = blockIdx.x * 128;
    const int wm = (wid >> 1) * 32;
    const int wn = (wid & 1) * 64;

    const __nv_bfloat16* B;
    void* Cv;
    int ksz, k0, sk;
    if (MODE == 2) {
        int pair = blockIdx.z >> 2, slice = blockIdx.z & 3;
        B = pair ? B2 : B1;
        Cv = pair ? C2v : C1v;
        sk = 4; ksz = K / 4; k0 = slice * ksz;
    } else {
        B = B1; Cv = C1v;
        sk = gridDim.z; ksz = K / sk; k0 = blockIdx.z * ksz;
    }
    const int nch = ksz >> 6;

    float acc[2][8][4];
#pragma unroll
    for (int mi = 0; mi < 2; mi++)
#pragma unroll
        for (int ni = 0; ni < 8; ni++)
#pragma unroll
            for (int q = 0; q < 4; q++) acc[mi][ni][q] = 0.f;

    int lrow[4], lcb[4];
    uint32_t lsw[4];
#pragma unroll
    for (int it = 0; it < 4; it++) {
        int u = tid + it * 256;
        lrow[it] = u >> 3;
        lcb[it]  = u & 7;
        lsw[it]  = sw128((uint32_t)(lrow[it] * 128 + lcb[it] * 16));
    }

    const int a_row = wm + (lane & 15);
    const int a_kof = (lane >> 4) * 8;
    const int b_row = wn + ((lane >> 4) << 3) + (lane & 7);
    const int b_kof = ((lane >> 3) & 1) * 8;

    auto issue = [&](int kc, int buf) {
        uint32_t sbuf = sbase + buf * 32768;
#pragma unroll
        for (int it = 0; it < 4; it++) {
            int col = k0 + kc * 64 + lcb[it] * 8;
            cp_async16(sbuf + lsw[it],         A + (size_t)(bm + lrow[it]) * K + col);
            cp_async16(sbuf + 16384 + lsw[it], B + (size_t)(bn + lrow[it]) * K + col);
        }
        cp_commit();
    };

    issue(0, 0);
    for (int g = 0; g < nch; g++) {
        if (g + 1 < nch) {
            issue(g + 1, (g + 1) & 1);
            asm volatile("cp.async.wait_group 1;" ::: "memory");
        } else {
            asm volatile("cp.async.wait_group 0;" ::: "memory");
        }
        __syncthreads();
        uint32_t sbuf = sbase + (g & 1) * 32768;
        const uint32_t sA = sbuf, sB = sbuf + 16384;
#pragma unroll
        for (int kk = 0; kk < 64; kk += 16) {
            uint32_t af[2][4], bf[4][4];
#pragma unroll
            for (int mi = 0; mi < 2; mi++)
                ldsm_x4(af[mi], sA + sw128((uint32_t)((a_row + mi * 16) * 128 + (kk + a_kof) * 2)));
#pragma unroll
            for (int np = 0; np < 4; np++)
                ldsm_x4(bf[np], sB + sw128((uint32_t)((b_row + np * 16) * 128 + (kk + b_kof) * 2)));
#pragma unroll
            for (int mi = 0; mi < 2; mi++)
#pragma unroll
                for (int ni = 0; ni < 8; ni++)
                    mma_bf16(acc[mi][ni], af[mi],
                             bf[ni >> 1][(ni & 1) * 2], bf[ni >> 1][(ni & 1) * 2 + 1]);
        }
        __syncthreads();
    }

    const int er = lane >> 2, ec = (lane & 3) * 2;
    if (MODE == 1) {
        __nv_bfloat16* C = (__nv_bfloat16*)Cv;
#pragma unroll
        for (int mi = 0; mi < 2; mi++) {
            int row0 = bm + wm + mi * 16 + er;
#pragma unroll
            for (int ni = 0; ni < 8; ni++) {
                int col = bn + wn + ni * 8 + ec;
                __nv_bfloat162 p0 = {__float2bfloat16(acc[mi][ni][0]),
                                     __float2bfloat16(acc[mi][ni][1])};
                __nv_bfloat162 p1 = {__float2bfloat16(acc[mi][ni][2]),
                                     __float2bfloat16(acc[mi][ni][3])};
                *reinterpret_cast<__nv_bfloat162*>(C + (size_t)row0 * N + col)       = p0;
                *reinterpret_cast<__nv_bfloat162*>(C + (size_t)(row0 + 8) * N + col) = p1;
            }
        }
    } else {
        float* C = (float*)Cv;
        if (MODE == 0 && sk == 1) {
#pragma unroll
            for (int mi = 0; mi < 2; mi++) {
                int row0 = bm + wm + mi * 16 + er;
#pragma unroll
                for (int ni = 0; ni < 8; ni++) {
                    int col = bn + wn + ni * 8 + ec;
                    *reinterpret_cast<float2*>(C + (size_t)row0 * N + col) =
                        make_float2(acc[mi][ni][0], acc[mi][ni][1]);
                    *reinterpret_cast<float2*>(C + (size_t)(row0 + 8) * N + col) =
                        make_float2(acc[mi][ni][2], acc[mi][ni][3]);
                }
            }
        } else {
#pragma unroll
            for (int mi = 0; mi < 2; mi++) {
                int row0 = bm + wm + mi * 16 + er;
#pragma unroll
                for (int ni = 0; ni < 8; ni++) {
                    int col = bn + wn + ni * 8 + ec;
                    atomicAdd(C + (size_t)row0 * N + col,       acc[mi][ni][0]);
                    atomicAdd(C + (size_t)row0 * N + col + 1,   acc[mi][ni][1]);
                    atomicAdd(C + (size_t)(row0 + 8) * N + col,     acc[mi][ni][2]);
                    atomicAdd(C + (size_t)(row0 + 8) * N + col + 1, acc[mi][ni][3]);
                }
            }
        }
    }
}

// ==================== sparse aggregation ====================
__global__ void gcn_agg_kernel(const float* __restrict__ xw, const float* __restrict__ bias,
                               float* __restrict__ out, int F, int do_tanh)
{
    int v = blockIdx.x, f = threadIdx.x;
    __shared__ int   sid[256];
    __shared__ float snw[256];
    int nb = d_cnt_in[v], base = d_off_in[v];
    float dv = d_dis_sp[v];
    float acc = 0.f;
    int CH = blockDim.x;
    for (int c0 = 0; c0 < nb; c0 += CH) {
        int m = min(CH, nb - c0);
        __syncthreads();
        if (f < m) {
            int r = d_csc_src[base + c0 + f];
            sid[f] = r;
            snw[f] = d_dis_sp[r];
        }
        __syncthreads();
#pragma unroll 4
        for (int e = 0; e < m; e++)
            acc += snw[e] * xw[(size_t)sid[e] * F + f];
    }
    float o = dv * acc + dv * dv * xw[(size_t)v * F + f] + bias[f];
    out[(size_t)v * F + f] = do_tanh ? tanhf(o) : o;
}

__global__ void gcn_agg_split_kernel(const float* __restrict__ xw, const float* __restrict__ bias,
                                     __nv_bfloat16* __restrict__ hi,
                                     __nv_bfloat16* __restrict__ lo, int F)
{
    int v = blockIdx.x, f = threadIdx.x;
    __shared__ int   sid[256];
    __shared__ float snw[256];
    int nb = d_cnt_in[v], base = d_off_in[v];
    float dv = d_dis_sp[v];
    float acc = 0.f;
    int CH = blockDim.x;
    for (int c0 = 0; c0 < nb; c0 += CH) {
        int m = min(CH, nb - c0);
        __syncthreads();
        if (f < m) {
            int r = d_csc_src[base + c0 + f];
            sid[f] = r;
            snw[f] = d_dis_sp[r];
        }
        __syncthreads();
#pragma unroll 4
        for (int e = 0; e < m; e++)
            acc += snw[e] * xw[(size_t)sid[e] * F + f];
    }
    float o = tanhf(dv * acc + dv * dv * xw[(size_t)v * F + f] + bias[f]);
    __nv_bfloat16 h = __float2bfloat16(o);
    hi[(size_t)v * F + f] = h;
    lo[(size_t)v * F + f] = __float2bfloat16(o - __bfloat162float(h));
}

__global__ void y_agg_split_kernel(const float* __restrict__ x2,
                                   __nv_bfloat16* __restrict__ hi,
                                   __nv_bfloat16* __restrict__ lo)
{
    int v = blockIdx.x, f = threadIdx.x;
    __shared__ int   sid[256];
    __shared__ float snw[256];
    int nb = d_cnt_out[v], base = d_off_out[v];
    float dv = d_dis_dn[v];
    float acc = 0.f;
    for (int c0 = 0; c0 < nb; c0 += 256) {
        int m = min(256, nb - c0);
        __syncthreads();
        if (f < m) {
            int c = d_csr_dst[base + c0 + f];
            sid[f] = c;
            snw[f] = (c == v) ? 0.f : d_dis_dn[c];
        }
        __syncthreads();
#pragma unroll 4
        for (int e = 0; e < m; e++)
            acc += snw[e] * x2[(size_t)sid[e] * HID + f];
    }
    float o = dv * acc + dv * dv * x2[(size_t)v * HID + f];
    __nv_bfloat16 h = __float2bfloat16(o);
    hi[(size_t)v * HID + f] = h;
    lo[(size_t)v * HID + f] = __float2bfloat16(o - __bfloat162float(h));
}

__global__ void t_agg_kernel(const __nv_bfloat16* __restrict__ sh, float* __restrict__ tt)
{
    int v = blockIdx.x, t = threadIdx.x;
    __shared__ int sid[256];
    int nb = d_cnt_out[v], base = d_off_out[v];
    float a0 = 0.f, a1 = 0.f, a2 = 0.f, a3 = 0.f;
    for (int c0 = 0; c0 < nb; c0 += 256) {
        int m = min(256, nb - c0);
        __syncthreads();
        if (t < m) sid[t] = d_csr_dst[base + c0 + t];
        __syncthreads();
#pragma unroll 4
        for (int e = 0; e < m; e++) {
            const __nv_bfloat16* xr = sh + (size_t)sid[e] * KCL;
            __nv_bfloat162 p0 = *reinterpret_cast<const __nv_bfloat162*>(xr + t * 2);
            a0 += __bfloat162float(p0.x);
            a1 += __bfloat162float(p0.y);
            __nv_bfloat162 p1 = *reinterpret_cast<const __nv_bfloat162*>(xr + 512 + t * 2);
            a2 += __bfloat162float(p1.x);
            a3 += __bfloat162float(p1.y);
        }
    }
    tt[(size_t)v * KCL + t * 2]       = a0;
    tt[(size_t)v * KCL + t * 2 + 1]   = a1;
    tt[(size_t)v * KCL + 512 + t * 2]     = a2;
    tt[(size_t)v * KCL + 512 + t * 2 + 1] = a3;
}

__global__ void softmax_ent_kernel(float* __restrict__ s, const float* __restrict__ bp,
                                   __nv_bfloat16* __restrict__ shi,
                                   __nv_bfloat16* __restrict__ slo)
{
    int v = blockIdx.x, t = threadIdx.x;
    float* row = s + (size_t)v * KCL;
    float x0 = row[t]       + bp[t];
    float x1 = row[t + 256] + bp[t + 256];
    float x2 = row[t + 512] + bp[t + 512];
    float x3 = row[t + 768] + bp[t + 768];
    __shared__ float red[256];
    float mx = fmaxf(fmaxf(x0, x1), fmaxf(x2, x3));
    red[t] = mx; __syncthreads();
    for (int o = 128; o > 0; o >>= 1) { if (t < o) red[t] = fmaxf(red[t], red[t + o]); __syncthreads(); }
    float m = red[0]; __syncthreads();
    float e0 = expf(x0 - m), e1 = expf(x1 - m), e2 = expf(x2 - m), e3 = expf(x3 - m);
    red[t] = e0 + e1 + e2 + e3; __syncthreads();
    for (int o = 128; o > 0; o >>= 1) { if (t < o) red[t] += red[t + o]; __syncthreads(); }
    float inv = 1.0f / red[0]; __syncthreads();
    float p0 = e0 * inv, p1 = e1 * inv, p2 = e2 * inv, p3 = e3 * inv;
    row[t] = p0; row[t + 256] = p1; row[t + 512] = p2; row[t + 768] = p3;
    __nv_bfloat16* hrow = shi + (size_t)v * KCL;
    __nv_bfloat16* lrow = slo + (size_t)v * KCL;
    float p[4] = {p0, p1, p2, p3};
#pragma unroll
    for (int q = 0; q < 4; q++) {
        __nv_bfloat16 h = __float2bfloat16(p[q]);
        hrow[t + q * 256] = h;
        lrow[t + q * 256] = __float2bfloat16(p[q] - __bfloat162float(h));
    }
    float ent = -(p0 * logf(p0 + 1e-15f) + p1 * logf(p1 + 1e-15f) +
                  p2 * logf(p2 + 1e-15f) + p3 * logf(p3 + 1e-15f));
    red[t] = ent; __syncthreads();
    for (int o = 128; o > 0; o >>= 1) { if (t < o) red[t] += red[t + o]; __syncthreads(); }
    if (t == 0) atomicAdd(&d_scal[0], (double)red[0]);
}

// merged link-loss reductions
__global__ void linkloss_kernel(const float* __restrict__ t_arr, const float* __restrict__ s_arr,
                                const float* __restrict__ G_arr)
{
    int b = blockIdx.x;
    if (b < 2048) {
        int slot = (b < 1024) ? 1 : 3;
        const float* a = (b < 1024) ? t_arr : G_arr;
        const float* c = (b < 1024) ? s_arr : G_arr;
        int n = (b < 1024) ? N_NODES * KCL : KCL * KCL;
        int lb = (b < 1024) ? b : b - 1024;
        int i = (lb * 256 + threadIdx.x) * 4;
        float p = 0.f;
        int stride = 1024 * 256 * 4;
        for (; i < n; i += stride) {
            float4 va = *reinterpret_cast<const float4*>(a + i);
            float4 vc = *reinterpret_cast<const float4*>(c + i);
            p += va.x * vc.x + va.y * vc.y + va.z * vc.z + va.w * vc.w;
        }
        __shared__ float red[256];
        red[threadIdx.x] = p; __syncthreads();
        for (int o = 128; o > 0; o >>= 1) {
            if (threadIdx.x < o) red[threadIdx.x] += red[threadIdx.x + o];
            __syncthreads();
        }
        if (threadIdx.x == 0) atomicAdd(&d_scal[slot], (double)red[0]);
    } else {
        int v = b - 2048;
        int t = threadIdx.x;
        int nb = d_cnt_out[v], base = d_off_out[v];
        int tot = 0;
        for (int i = t; i < nb; i += blockDim.x) {
            int ci = d_csr_dst[base + i];
            int c = 0;
            for (int j = 0; j < nb; j++) c += (d_csr_dst[base + j] == ci) ? 1 : 0;
            tot += c;
        }
        __shared__ int redi[256];
        redi[t] = tot; __syncthreads();
        for (int o = 128; o > 0; o >>= 1) {
            if (t < o) redi[t] += redi[t + o];
            __syncthreads();
        }
        if (t == 0 && redi[0] != 0) atomicAdd(&d_scal[2], (double)redi[0]);
    }
}

__global__ void finalize_kernel(float* __restrict__ out_link, float* __restrict__ out_ent)
{
    double v = d_scal[2] - 2.0 * d_scal[1] + d_scal[3];
    if (v < 0.0) v = 0.0;
    *out_link = (float)(0.1 * sqrt(v) / ((double)N_NODES * (double)N_NODES));
    *out_ent  = (float)(0.1 * (d_scal[0] / (double)N_NODES));
}

// ==================== host side ====================
static cudaStream_t g_s1;
static cudaEvent_t  g_evFork, g_evJoin;
static int g_init_done = 0;

static void gemm3_s(cudaStream_t st, const __nv_bfloat16* Ah, const __nv_bfloat16* Al,
                    const __nv_bfloat16* Bh, const __nv_bfloat16* Bl,
                    float* C, int M, int N, int K, int SK)
{
    gemm3_mma_kernel<<<dim3(N / 128, M / 128, SK), 256, GEMM3_SMEM_BYTES, st>>>(
        Ah, Al, Bh, Bl, C, M, N, K);
}
static void gemm1_s(cudaStream_t st, const __nv_bfloat16* A, const __nv_bfloat16* B,
                    float* C, int M, int N, int K, int SK)
{
    gemm1_mma_kernel<0><<<dim3(N / 128, M / 128, SK), 256, GEMM1_SMEM_BYTES, st>>>(
        A, B, C, nullptr, nullptr, M, N, K);
}
static void gemm1_bf16_s(cudaStream_t st, const __nv_bfloat16* A, const __nv_bfloat16* B,
                         __nv_bfloat16* C, int M, int N, int K)
{
    gemm1_mma_kernel<1><<<dim3(N / 128, M / 128, 1), 256, GEMM1_SMEM_BYTES, st>>>(
        A, B, C, nullptr, nullptr, M, N, K);
}
static void gemm1_pair_s(cudaStream_t st, const __nv_bfloat16* A,
                         const __nv_bfloat16* B1, float* C1,
                         const __nv_bfloat16* B2, float* C2, int M, int N, int K)
{
    gemm1_mma_kernel<2><<<dim3(N / 128, M / 128, 8), 256, GEMM1_SMEM_BYTES, st>>>(
        A, B1, C1, B2, C2, M, N, K);
}
static void split_s(cudaStream_t st, const float* in, __nv_bfloat16* hi, __nv_bfloat16* lo, int n)
{
    split_kernel<<<(n / 4 + 255) / 256, 256, 0, st>>>(in, hi, lo, n);
}
static void tsplit_s(cudaStream_t st, const float* in, __nv_bfloat16* hi, __nv_bfloat16* lo,
                     int R, int C)
{
    tsplit_kernel<<<dim3(C / 32, R / 32), dim3(32, 8), 0, st>>>(in, hi, lo, R, C);
}

extern "C" void kernel_launch(void* const* d_in, const int* in_sizes, int n_in,
                              void* d_out, int out_size)
{
    if (!g_init_done) {
        cudaFuncSetAttribute(gemm3_mma_kernel, cudaFuncAttributeMaxDynamicSharedMemorySize,
                             GEMM3_SMEM_BYTES);
        cudaFuncSetAttribute(gemm1_mma_kernel<0>, cudaFuncAttributeMaxDynamicSharedMemorySize,
                             GEMM1_SMEM_BYTES);
        cudaFuncSetAttribute(gemm1_mma_kernel<1>, cudaFuncAttributeMaxDynamicSharedMemorySize,
                             GEMM1_SMEM_BYTES);
        cudaFuncSetAttribute(gemm1_mma_kernel<2>, cudaFuncAttributeMaxDynamicSharedMemorySize,
                             GEMM1_SMEM_BYTES);
        cudaStreamCreateWithFlags(&g_s1, cudaStreamNonBlocking);
        cudaEventCreateWithFlags(&g_evFork, cudaEventDisableTiming);
        cudaEventCreateWithFlags(&g_evJoin, cudaEventDisableTiming);
        g_init_done = 1;
    }
    cudaStream_t S0 = 0;         // capture (default) stream
    cudaStream_t S1 = g_s1;      // forked chain-D stream

    const float* nodes = (const float*)d_in[0];
    const int*   ei    = (const int*)d_in[1];
    const float* W1 = (const float*)d_in[3];  const float* b1 = (const float*)d_in[4];
    const float* W2 = (const float*)d_in[5];  const float* b2 = (const float*)d_in[6];
    const float* Wp = (const float*)d_in[7];  const float* bp = (const float*)d_in[8];
    const float* W3 = (const float*)d_in[9];  const float* b3 = (const float*)d_in[10];
    const float* W4 = (const float*)d_in[11]; const float* b4 = (const float*)d_in[12];
    const float* W5 = (const float*)d_in[13]; const float* b5 = (const float*)d_in[14];
    int E = in_sizes[1] / 2;

    float* out      = (float*)d_out;
    float* out_x    = out;
    float* out_adj  = out + (size_t)N_NODES * FEAT;
    float* out_link = out + (size_t)N_NODES * FEAT + (size_t)N_NODES * N_NODES;
    float* out_ent  = out_link + 1;

    float *xwA,*xwB,*xwC,*xwD,*xwE,*x2,*s,*t,*xp,*adjp,*G,*xo;
    cudaGetSymbolAddress((void**)&xwA,  g_xwA);
    cudaGetSymbolAddress((void**)&xwB,  g_xwB);
    cudaGetSymbolAddress((void**)&xwC,  g_xwC);
    cudaGetSymbolAddress((void**)&xwD,  g_xwD);
    cudaGetSymbolAddress((void**)&xwE,  g_xwE);
    cudaGetSymbolAddress((void**)&x2,   g_x2);
    cudaGetSymbolAddress((void**)&s,    g_s);
    cudaGetSymbolAddress((void**)&t,    g_t);
    cudaGetSymbolAddress((void**)&xp,   g_xp);
    cudaGetSymbolAddress((void**)&adjp, g_adjp);
    cudaGetSymbolAddress((void**)&G,    g_G);
    cudaGetSymbolAddress((void**)&xo,   g_xo);

    __nv_bfloat16 *nhi,*nlo,*xhi,*xlo,*shi,*slo,*sthi,*stlo,*x2thi,*x2tlo,*tthi,*ttlo;
    __nv_bfloat16 *xpthi,*xptlo,*apthi,*aptlo,*mbhi;
    __nv_bfloat16 *w1hi,*w1lo,*w2hi,*w2lo,*wphi,*wplo,*w3hi,*w3lo,*w4hi,*w4lo,*w5hi,*w5lo;
    cudaGetSymbolAddress((void**)&nhi,  g_nhi);  cudaGetSymbolAddress((void**)&nlo,  g_nlo);
    cudaGetSymbolAddress((void**)&xhi,  g_xhi);  cudaGetSymbolAddress((void**)&xlo,  g_xlo);
    cudaGetSymbolAddress((void**)&shi,  g_shi);  cudaGetSymbolAddress((void**)&slo,  g_slo);
    cudaGetSymbolAddress((void**)&sthi, g_sthi); cudaGetSymbolAddress((void**)&stlo, g_stlo);
    cudaGetSymbolAddress((void**)&x2thi,g_x2thi);cudaGetSymbolAddress((void**)&x2tlo,g_x2tlo);
    cudaGetSymbolAddress((void**)&tthi, g_tthi); cudaGetSymbolAddress((void**)&ttlo, g_ttlo);
    cudaGetSymbolAddress((void**)&xpthi,g_xpthi);cudaGetSymbolAddress((void**)&xptlo,g_xptlo);
    cudaGetSymbolAddress((void**)&apthi,g_apthi);cudaGetSymbolAddress((void**)&aptlo,g_aptlo);
    cudaGetSymbolAddress((void**)&mbhi, g_mbhi);
    cudaGetSymbolAddress((void**)&w1hi, g_w1hi); cudaGetSymbolAddress((void**)&w1lo, g_w1lo);
    cudaGetSymbolAddress((void**)&w2hi, g_w2hi); cudaGetSymbolAddress((void**)&w2lo, g_w2lo);
    cudaGetSymbolAddress((void**)&wphi, g_wphi); cudaGetSymbolAddress((void**)&wplo, g_wplo);
    cudaGetSymbolAddress((void**)&w3hi, g_w3hi); cudaGetSymbolAddress((void**)&w3lo, g_w3lo);
    cudaGetSymbolAddress((void**)&w4hi, g_w4hi); cudaGetSymbolAddress((void**)&w4lo, g_w4lo);
    cudaGetSymbolAddress((void**)&w5hi, g_w5hi); cudaGetSymbolAddress((void**)&w5lo, g_w5lo);

    // ---- batched weight transpose + buffer zero + graph prep ----
    TBatch tb;
    int acc_t = 0;
    auto set_m = [&](int i, const float* src, __nv_bfloat16* hi, __nv_bfloat16* lo, int R, int C) {
        acc_t += (C / 32) * (R / 32);
        tb.m[i] = TMat{src, hi, lo, R, C, acc_t};
    };
    set_m(0, W1, w1hi, w1lo, FEAT, HID);
    set_m(1, W2, w2hi, w2lo, HID, HID);
    set_m(2, Wp, wphi, wplo, HID, KCL);
    set_m(3, W3, w3hi, w3lo, HID, HID);
    set_m(4, W4, w4hi, w4lo, HID, HID);
    set_m(5, W5, w5hi, w5lo, HID, FEAT);
    tsplit_batch_kernel<<<acc_t, dim3(32, 8)>>>(tb);
    zero_all_kernel<<<1024, 256>>>();
    init_zero_kernel<<<(N_NODES + 255) / 256, 256>>>();
    count_kernel<<<(E + 255) / 256, 256>>>(ei, E);
    scan_kernel<<<1, 1024>>>();
    fill_kernel<<<(E + 255) / 256, 256>>>(ei, E);
    split_s(S0, nodes, nhi, nlo, N_NODES * FEAT);

    // ---- encoder ----
    gemm3_s(S0, nhi, nlo, w1hi, w1lo, xwA, N_NODES, HID, FEAT, 2);
    gcn_agg_split_kernel<<<N_NODES, HID>>>(xwA, b1, xhi, xlo, HID);
    gemm3_s(S0, xhi, xlo, w2hi, w2lo, xwB, N_NODES, HID, HID, 4);
    gcn_agg_kernel<<<N_NODES, HID>>>(xwB, b2, x2, HID, 1);

    // ---- assignment ----
    y_agg_split_kernel<<<N_NODES, HID>>>(x2, xhi, xlo);
    gemm3_s(S0, xhi, xlo, wphi, wplo, s, N_NODES, KCL, HID, 1);
    softmax_ent_kernel<<<N_NODES, 256>>>(s, bp, shi, slo);

    // shared prerequisites for both chains
    tsplit_s(S0, s, sthi, stlo, N_NODES, KCL);     // S^T
    tsplit_s(S0, x2, x2thi, x2tlo, N_NODES, HID);  // x2^T

    // ======== FORK: chain D (xp -> xo -> decoder) on S1 ========
    cudaEventRecord(g_evFork, S0);
    cudaStreamWaitEvent(S1, g_evFork, 0);

    gemm3_s(S1, sthi, stlo, x2thi, x2tlo, xp, KCL, HID, N_NODES, 16);   // xp = S^T x2
    tsplit_s(S1, xp, xpthi, xptlo, KCL, HID);
    gemm3_s(S1, shi, slo, xpthi, xptlo, xo, N_NODES, HID, KCL, 4);      // xo = S xp
    split_s(S1, xo, xhi, xlo, N_NODES * HID);
    gemm3_s(S1, xhi, xlo, w3hi, w3lo, xwC, N_NODES, HID, HID, 4);
    gcn_agg_split_kernel<<<N_NODES, HID, 0, S1>>>(xwC, b3, xhi, xlo, HID);
    gemm3_s(S1, xhi, xlo, w4hi, w4lo, xwD, N_NODES, HID, HID, 4);
    gcn_agg_split_kernel<<<N_NODES, HID, 0, S1>>>(xwD, b4, xhi, xlo, HID);
    gemm3_s(S1, xhi, xlo, w5hi, w5lo, xwE, N_NODES, FEAT, HID, 4);
    gcn_agg_kernel<<<N_NODES, FEAT, 0, S1>>>(xwE, b5, out_x, FEAT, 0);
    cudaEventRecord(g_evJoin, S1);

    // ======== chain P (adjacency) stays on S0 ========
    t_agg_kernel<<<N_NODES, 256>>>(shi, t);                       // t = A S
    tsplit_s(S0, t, tthi, ttlo, N_NODES, KCL);
    gemm1_pair_s(S0, sthi, tthi, adjp, sthi, G, KCL, KCL, N_NODES);  // adjp & G
    linkloss_kernel<<<6144, 256>>>(t, s, G);
    tsplit_s(S0, adjp, apthi, aptlo, KCL, KCL);
    gemm1_bf16_s(S0, shi, apthi, mbhi, N_NODES, KCL, KCL);        // Mb = S adjp
    gemm1_s(S0, mbhi, shi, out_adj, N_NODES, N_NODES, KCL, 1);    // adj_out
    finalize_kernel<<<1, 1>>>(out_link, out_ent);

    // ======== JOIN ========
    cudaStreamWaitEvent(S0, g_evJoin, 0);
}

// round 16
// speedup vs baseline: 1.1005x; 1.0079x over previous
#include <cuda_runtime.h>
#include <cuda_bf16.h>
#include <math.h>
#include <stdint.h>

// Problem constants (fixed for this dataset)
#define N_NODES 4096
#define FEAT    128
#define HID     256
#define KCL     1024
#define NE      131072

// ==================== device scratch ====================
__device__ __align__(16) int   d_cnt_in [N_NODES];
__device__ __align__(16) int   d_cnt_out[N_NODES];
__device__ __align__(16) int   d_selfc  [N_NODES];
__device__ __align__(16) int   d_cur_in [N_NODES];
__device__ __align__(16) int   d_cur_out[N_NODES];
__device__ __align__(16) int   d_off_in [N_NODES];
__device__ __align__(16) int   d_off_out[N_NODES];
__device__ __align__(16) int   d_csc_src[NE];
__device__ __align__(16) int   d_csr_dst[NE];
__device__ __align__(16) float d_dis_sp [N_NODES];
__device__ __align__(16) float d_dis_dn [N_NODES];
__device__ double d_scal[4];   // [0]=ent [1]=cross [2]=sum adj^2 [3]=||G||^2

// fp32 buffers (distinct per split-K GEMM output so they can be pre-zeroed once)
__device__ __align__(16) float g_xwA[N_NODES*HID];   // enc1 out (SK2)
__device__ __align__(16) float g_xwB[N_NODES*HID];   // enc2 out (SK4)
__device__ __align__(16) float g_xwC[N_NODES*HID];   // dec3 out (SK4)
__device__ __align__(16) float g_xwD[N_NODES*HID];   // dec4 out (SK4)
__device__ __align__(16) float g_xwE[N_NODES*FEAT];  // dec5 out (SK4)
__device__ __align__(16) float g_x2 [N_NODES*HID];
__device__ __align__(16) float g_s  [N_NODES*KCL];
__device__ __align__(16) float g_t  [N_NODES*KCL];
__device__ __align__(16) float g_xp [KCL*HID];       // SK16
__device__ __align__(16) float g_adjp[KCL*KCL];      // SK4
__device__ __align__(16) float g_G  [KCL*KCL];       // SK4
__device__ __align__(16) float g_xo [N_NODES*HID];   // SK4

// bf16 split operand buffers
__device__ __align__(16) __nv_bfloat16 g_nhi [N_NODES*FEAT],  g_nlo [N_NODES*FEAT];
__device__ __align__(16) __nv_bfloat16 g_xhi [N_NODES*HID],   g_xlo [N_NODES*HID];
__device__ __align__(16) __nv_bfloat16 g_shi [N_NODES*KCL],   g_slo [N_NODES*KCL];
__device__ __align__(16) __nv_bfloat16 g_sthi[KCL*N_NODES],   g_stlo[KCL*N_NODES];
__device__ __align__(16) __nv_bfloat16 g_x2thi[HID*N_NODES],  g_x2tlo[HID*N_NODES];
__device__ __align__(16) __nv_bfloat16 g_tthi[KCL*N_NODES],   g_ttlo[KCL*N_NODES];
__device__ __align__(16) __nv_bfloat16 g_xpthi[HID*KCL],      g_xptlo[HID*KCL];
__device__ __align__(16) __nv_bfloat16 g_apthi[KCL*KCL],      g_aptlo[KCL*KCL];
__device__ __align__(16) __nv_bfloat16 g_mbhi[N_NODES*KCL];
// per-weight transposed bf16 buffers
__device__ __align__(16) __nv_bfloat16 g_w1hi[HID*FEAT], g_w1lo[HID*FEAT];
__device__ __align__(16) __nv_bfloat16 g_w2hi[HID*HID],  g_w2lo[HID*HID];
__device__ __align__(16) __nv_bfloat16 g_wphi[KCL*HID],  g_wplo[KCL*HID];
__device__ __align__(16) __nv_bfloat16 g_w3hi[HID*HID],  g_w3lo[HID*HID];
__device__ __align__(16) __nv_bfloat16 g_w4hi[HID*HID],  g_w4lo[HID*HID];
__device__ __align__(16) __nv_bfloat16 g_w5hi[FEAT*HID], g_w5lo[FEAT*HID];

// ==================== setup kernels ====================
__global__ void init_zero_kernel() {
    int i = blockIdx.x * blockDim.x + threadIdx.x;
    if (i < N_NODES) {
        d_cnt_in[i] = 0; d_cnt_out[i] = 0; d_selfc[i] = 0;
        d_cur_in[i] = 0; d_cur_out[i] = 0;
    }
    if (i < 4) d_scal[i] = 0.0;
}

// one launch: zero every split-K destination buffer
__global__ void zero_all_kernel() {
    size_t stride = (size_t)gridDim.x * blockDim.x * 4;
    size_t base = ((size_t)blockIdx.x * blockDim.x + threadIdx.x) * 4;
#define ZSEG(arr, n) \
    for (size_t i = base; i < (size_t)(n); i += stride) \
        *reinterpret_cast<float4*>((arr) + i) = make_float4(0.f, 0.f, 0.f, 0.f);
    ZSEG(g_xwA, N_NODES * HID)
    ZSEG(g_xwB, N_NODES * HID)
    ZSEG(g_xwC, N_NODES * HID)
    ZSEG(g_xwD, N_NODES * HID)
    ZSEG(g_xwE, N_NODES * FEAT)
    ZSEG(g_xp,  KCL * HID)
    ZSEG(g_adjp, KCL * KCL)
    ZSEG(g_G,   KCL * KCL)
    ZSEG(g_xo,  N_NODES * HID)
#undef ZSEG
}

__global__ void count_kernel(const int* __restrict__ ei, int E) {
    int e = blockIdx.x * blockDim.x + threadIdx.x;
    if (e >= E) return;
    int r = ei[e];
    int c = ei[E + e];
    atomicAdd(&d_cnt_out[r], 1);
    atomicAdd(&d_cnt_in[c], 1);
    if (r == c) atomicAdd(&d_selfc[r], 1);
}

__global__ void scan_kernel() {
    __shared__ int sh[1024];
    int t = threadIdx.x;
    {
        int v = t * 4;
        int a0 = d_cnt_in[v], a1 = d_cnt_in[v+1], a2 = d_cnt_in[v+2], a3 = d_cnt_in[v+3];
        int tot = a0 + a1 + a2 + a3;
        sh[t] = tot; __syncthreads();
        for (int o = 1; o < 1024; o <<= 1) {
            int x = (t >= o) ? sh[t - o] : 0;
            __syncthreads();
            sh[t] += x;
            __syncthreads();
        }
        int excl = sh[t] - tot;
        d_off_in[v]   = excl;
        d_off_in[v+1] = excl + a0;
        d_off_in[v+2] = excl + a0 + a1;
        d_off_in[v+3] = excl + a0 + a1 + a2;
        d_dis_sp[v]   = rsqrtf((float)(a0 + 1));
        d_dis_sp[v+1] = rsqrtf((float)(a1 + 1));
        d_dis_sp[v+2] = rsqrtf((float)(a2 + 1));
        d_dis_sp[v+3] = rsqrtf((float)(a3 + 1));
        __syncthreads();
    }
    {
        int v = t * 4;
        int a0 = d_cnt_out[v], a1 = d_cnt_out[v+1], a2 = d_cnt_out[v+2], a3 = d_cnt_out[v+3];
        int tot = a0 + a1 + a2 + a3;
        sh[t] = tot; __syncthreads();
        for (int o = 1; o < 1024; o <<= 1) {
            int x = (t >= o) ? sh[t - o] : 0;
            __syncthreads();
            sh[t] += x;
            __syncthreads();
        }
        int excl = sh[t] - tot;
        d_off_out[v]   = excl;
        d_off_out[v+1] = excl + a0;
        d_off_out[v+2] = excl + a0 + a1;
        d_off_out[v+3] = excl + a0 + a1 + a2;
        d_dis_dn[v]   = rsqrtf((float)(a0 - d_selfc[v]   + 1));
        d_dis_dn[v+1] = rsqrtf((float)(a1 - d_selfc[v+1] + 1));
        d_dis_dn[v+2] = rsqrtf((float)(a2 - d_selfc[v+2] + 1));
        d_dis_dn[v+3] = rsqrtf((float)(a3 - d_selfc[v+3] + 1));
    }
}

__global__ void fill_kernel(const int* __restrict__ ei, int E) {
    int e = blockIdx.x * blockDim.x + threadIdx.x;
    if (e >= E) return;
    int r = ei[e];
    int c = ei[E + e];
    int p = atomicAdd(&d_cur_in[c], 1);
    d_csc_src[d_off_in[c] + p] = r;
    int q = atomicAdd(&d_cur_out[r], 1);
    d_csr_dst[d_off_out[r] + q] = c;
}

// ==================== split / transpose-split ====================
__global__ void split_kernel(const float* __restrict__ in,
                             __nv_bfloat16* __restrict__ hi,
                             __nv_bfloat16* __restrict__ lo, int n)
{
    int i = (blockIdx.x * blockDim.x + threadIdx.x) * 4;
    if (i >= n) return;
    float4 v = *reinterpret_cast<const float4*>(in + i);
    __nv_bfloat16 h0 = __float2bfloat16(v.x);
    __nv_bfloat16 h1 = __float2bfloat16(v.y);
    __nv_bfloat16 h2 = __float2bfloat16(v.z);
    __nv_bfloat16 h3 = __float2bfloat16(v.w);
    __nv_bfloat162 hh0 = {h0, h1}, hh1 = {h2, h3};
    *reinterpret_cast<__nv_bfloat162*>(hi + i)     = hh0;
    *reinterpret_cast<__nv_bfloat162*>(hi + i + 2) = hh1;
    __nv_bfloat162 ll0 = {__float2bfloat16(v.x - __bfloat162float(h0)),
                          __float2bfloat16(v.y - __bfloat162float(h1))};
    __nv_bfloat162 ll1 = {__float2bfloat16(v.z - __bfloat162float(h2)),
                          __float2bfloat16(v.w - __bfloat162float(h3))};
    *reinterpret_cast<__nv_bfloat162*>(lo + i)     = ll0;
    *reinterpret_cast<__nv_bfloat162*>(lo + i + 2) = ll1;
}

// shared transpose-split body
__device__ __forceinline__ void tsplit_body(const float* in, __nv_bfloat16* hi,
                                            __nv_bfloat16* lo, int R, int C,
                                            int c0, int r0)
{
    __shared__ float tile[32][33];
    int tx = threadIdx.x, ty = threadIdx.y;  // 32 x 8
#pragma unroll
    for (int j = 0; j < 32; j += 8)
        tile[ty + j][tx] = in[(size_t)(r0 + ty + j) * C + c0 + tx];
    __syncthreads();
#pragma unroll
    for (int j = 0; j < 32; j += 8) {
        float x = tile[tx][ty + j];
        __nv_bfloat16 h = __float2bfloat16(x);
        size_t o = (size_t)(c0 + ty + j) * R + r0 + tx;
        hi[o] = h;
        lo[o] = __float2bfloat16(x - __bfloat162float(h));
    }
}

__global__ void tsplit_kernel(const float* __restrict__ in,
                              __nv_bfloat16* __restrict__ hi,
                              __nv_bfloat16* __restrict__ lo, int R, int C)
{
    tsplit_body(in, hi, lo, R, C, blockIdx.x * 32, blockIdx.y * 32);
}

// batched weight transpose-split: all 6 W matrices in one launch
struct TMat { const float* src; __nv_bfloat16* hi; __nv_bfloat16* lo; int R, C, tile_end; };
struct TBatch { TMat m[6]; };
__global__ void tsplit_batch_kernel(TBatch tb)
{
    int b = blockIdx.x;
    int i = 0;
    while (b >= tb.m[i].tile_end) i++;
    int lt = b - (i == 0 ? 0 : tb.m[i - 1].tile_end);
    int tilesX = tb.m[i].C / 32;
    int c0 = (lt % tilesX) * 32;
    int r0 = (lt / tilesX) * 32;
    tsplit_body(tb.m[i].src, tb.m[i].hi, tb.m[i].lo, tb.m[i].R, tb.m[i].C, c0, r0);
}

// ==================== HMMA common helpers ====================
__device__ __forceinline__ uint32_t smem_u32(const void* p) {
    uint32_t a;
    asm("{ .reg .u64 t; cvta.to.shared.u64 t, %1; cvt.u32.u64 %0, t; }" : "=r"(a) : "l"(p));
    return a;
}
__device__ __forceinline__ void cp_async16(uint32_t saddr, const void* gaddr) {
    asm volatile("cp.async.cg.shared.global [%0], [%1], 16;" :: "r"(saddr), "l"(gaddr));
}
__device__ __forceinline__ void cp_commit() {
    asm volatile("cp.async.commit_group;");
}
__device__ __forceinline__ void ldsm_x4(uint32_t* r, uint32_t addr) {
    asm volatile("ldmatrix.sync.aligned.m8n8.x4.shared.b16 {%0,%1,%2,%3}, [%4];"
        : "=r"(r[0]), "=r"(r[1]), "=r"(r[2]), "=r"(r[3]) : "r"(addr));
}
__device__ __forceinline__ void mma_bf16(float* d, const uint32_t* a, uint32_t b0, uint32_t b1) {
    asm volatile(
        "mma.sync.aligned.m16n8k16.row.col.f32.bf16.bf16.f32 "
        "{%0,%1,%2,%3}, {%4,%5,%6,%7}, {%8,%9}, {%0,%1,%2,%3};"
        : "+f"(d[0]), "+f"(d[1]), "+f"(d[2]), "+f"(d[3])
        : "r"(a[0]), "r"(a[1]), "r"(a[2]), "r"(a[3]), "r"(b0), "r"(b1));
}
__device__ __forceinline__ uint32_t sw128(uint32_t off) {
    return off ^ ((off >> 3) & 0x70);
}

// ==================== 3-term fused split GEMM ====================
#define GEMM3_SMEM_BYTES 131072

__global__ __launch_bounds__(256) void gemm3_mma_kernel(
    const __nv_bfloat16* __restrict__ Ahi, const __nv_bfloat16* __restrict__ Alo,
    const __nv_bfloat16* __restrict__ Bhi, const __nv_bfloat16* __restrict__ Blo,
    float* __restrict__ C, int M, int N, int K)
{
    extern __shared__ char smem[];
    const uint32_t sbase = smem_u32(smem);
    const int tid = threadIdx.x, lane = tid & 31, wid = tid >> 5;
    const int bm = blockIdx.y * 128, bn = blockIdx.x * 128;
    const int wm = (wid >> 1) * 32;
    const int wn = (wid & 1) * 64;

    const int ksz = K / gridDim.z;
    const int k0  = blockIdx.z * ksz;
    const int nch = ksz >> 6;

    float acc[2][8][4];
#pragma unroll
    for (int mi = 0; mi < 2; mi++)
#pragma unroll
        for (int ni = 0; ni < 8; ni++)
#pragma unroll
            for (int q = 0; q < 4; q++) acc[mi][ni][q] = 0.f;

    int lrow[4], lcb[4];
    uint32_t lsw[4];
#pragma unroll
    for (int it = 0; it < 4; it++) {
        int u = tid + it * 256;
        lrow[it] = u >> 3;
        lcb[it]  = u & 7;
        lsw[it]  = sw128((uint32_t)(lrow[it] * 128 + lcb[it] * 16));
    }

    const int a_row = wm + (lane & 15);
    const int a_kof = (lane >> 4) * 8;
    const int b_row = wn + ((lane >> 4) << 3) + (lane & 7);
    const int b_kof = ((lane >> 3) & 1) * 8;

    auto issue = [&](int kc, int buf) {
        uint32_t sbuf = sbase + buf * 65536;
        const __nv_bfloat16* tp[4] = { Ahi, Alo, Bhi, Blo };
#pragma unroll
        for (int tI = 0; tI < 4; tI++) {
            int ro = (tI < 2) ? bm : bn;
            const __nv_bfloat16* P = tp[tI];
            uint32_t sdst = sbuf + tI * 16384;
#pragma unroll
            for (int it = 0; it < 4; it++)
                cp_async16(sdst + lsw[it],
                           P + (size_t)(ro + lrow[it]) * K + k0 + kc * 64 + lcb[it] * 8);
        }
        cp_commit();
    };

    issue(0, 0);
    for (int g = 0; g < nch; g++) {
        if (g + 1 < nch) {
            issue(g + 1, (g + 1) & 1);
            asm volatile("cp.async.wait_group 1;" ::: "memory");
        } else {
            asm volatile("cp.async.wait_group 0;" ::: "memory");
        }
        __syncthreads();
        uint32_t sbuf = sbase + (g & 1) * 65536;
        const uint32_t sAh = sbuf, sAl = sbuf + 16384, sBh = sbuf + 32768, sBl = sbuf + 49152;
#pragma unroll
        for (int kk = 0; kk < 64; kk += 16) {
            uint32_t ah[2][4], al[2][4], bh[4][4], bl[4][4];
#pragma unroll
            for (int mi = 0; mi < 2; mi++) {
                uint32_t off = sw128((uint32_t)((a_row + mi * 16) * 128 + (kk + a_kof) * 2));
                ldsm_x4(ah[mi], sAh + off);
                ldsm_x4(al[mi], sAl + off);
            }
#pragma unroll
            for (int np = 0; np < 4; np++) {
                uint32_t off = sw128((uint32_t)((b_row + np * 16) * 128 + (kk + b_kof) * 2));
                ldsm_x4(bh[np], sBh + off);
                ldsm_x4(bl[np], sBl + off);
            }
#pragma unroll
            for (int mi = 0; mi < 2; mi++)
#pragma unroll
                for (int ni = 0; ni < 8; ni++) {
                    uint32_t b0h = bh[ni >> 1][(ni & 1) * 2], b1h = bh[ni >> 1][(ni & 1) * 2 + 1];
                    uint32_t b0l = bl[ni >> 1][(ni & 1) * 2], b1l = bl[ni >> 1][(ni & 1) * 2 + 1];
                    mma_bf16(acc[mi][ni], ah[mi], b0h, b1h);
                    mma_bf16(acc[mi][ni], al[mi], b0h, b1h);
                    mma_bf16(acc[mi][ni], ah[mi], b0l, b1l);
                }
        }
        __syncthreads();
    }

    const int er = lane >> 2, ec = (lane & 3) * 2;
    if (gridDim.z == 1) {
#pragma unroll
        for (int mi = 0; mi < 2; mi++) {
            int row0 = bm + wm + mi * 16 + er;
#pragma unroll
            for (int ni = 0; ni < 8; ni++) {
                int col = bn + wn + ni * 8 + ec;
                *reinterpret_cast<float2*>(C + (size_t)row0 * N + col) =
                    make_float2(acc[mi][ni][0], acc[mi][ni][1]);
                *reinterpret_cast<float2*>(C + (size_t)(row0 + 8) * N + col) =
                    make_float2(acc[mi][ni][2], acc[mi][ni][3]);
            }
        }
    } else {
#pragma unroll
        for (int mi = 0; mi < 2; mi++) {
            int row0 = bm + wm + mi * 16 + er;
#pragma unroll
            for (int ni = 0; ni < 8; ni++) {
                int col = bn + wn + ni * 8 + ec;
                atomicAdd(C + (size_t)row0 * N + col,       acc[mi][ni][0]);
                atomicAdd(C + (size_t)row0 * N + col + 1,   acc[mi][ni][1]);
                atomicAdd(C + (size_t)(row0 + 8) * N + col,     acc[mi][ni][2]);
                atomicAdd(C + (size_t)(row0 + 8) * N + col + 1, acc[mi][ni][3]);
            }
        }
    }
}

// ==================== 1-term plain bf16 GEMM (positive chains) ====================
#define GEMM1_SMEM_BYTES 65536

// MODE 0: fp32 out (SK via atomics); MODE 1: bf16 out (SK=1);
// MODE 2: paired (z encodes pair<<2|slice)
template <int MODE>
__global__ __launch_bounds__(256) void gemm1_mma_kernel(
    const __nv_bfloat16* __restrict__ A,
    const __nv_bfloat16* __restrict__ B1, void* __restrict__ C1v,
    const __nv_bfloat16* __restrict__ B2, void* __restrict__ C2v,
    int M, int N, int K)
{
    extern __shared__ char smem[];
    const uint32_t sbase = smem_u32(smem);
    const int tid = threadIdx.x, lane = tid & 31, wid = tid >> 5;
    const int bm = blockIdx.y * 128, bn = blockIdx.x * 128;
    const int wm = (wid >> 1) * 32;
    const int wn = (wid & 1) * 64;

    const __nv_bfloat16* B;
    void* Cv;
    int ksz, k0, sk;
    if (MODE == 2) {
        int pair = blockIdx.z >> 2, slice = blockIdx.z & 3;
        B = pair ? B2 : B1;
        Cv = pair ? C2v : C1v;
        sk = 4; ksz = K / 4; k0 = slice * ksz;
    } else {
        B = B1; Cv = C1v;
        sk = gridDim.z; ksz = K / sk; k0 = blockIdx.z * ksz;
    }
    const int nch = ksz >> 6;

    float acc[2][8][4];
#pragma unroll
    for (int mi = 0; mi < 2; mi++)
#pragma unroll
        for (int ni = 0; ni < 8; ni++)
#pragma unroll
            for (int q = 0; q < 4; q++) acc[mi][ni][q] = 0.f;

    int lrow[4], lcb[4];
    uint32_t lsw[4];
#pragma unroll
    for (int it = 0; it < 4; it++) {
        int u = tid + it * 256;
        lrow[it] = u >> 3;
        lcb[it]  = u & 7;
        lsw[it]  = sw128((uint32_t)(lrow[it] * 128 + lcb[it] * 16));
    }

    const int a_row = wm + (lane & 15);
    const int a_kof = (lane >> 4) * 8;
    const int b_row = wn + ((lane >> 4) << 3) + (lane & 7);
    const int b_kof = ((lane >> 3) & 1) * 8;

    auto issue = [&](int kc, int buf) {
        uint32_t sbuf = sbase + buf * 32768;
#pragma unroll
        for (int it = 0; it < 4; it++) {
            int col = k0 + kc * 64 + lcb[it] * 8;
            cp_async16(sbuf + lsw[it],         A + (size_t)(bm + lrow[it]) * K + col);
            cp_async16(sbuf + 16384 + lsw[it], B + (size_t)(bn + lrow[it]) * K + col);
        }
        cp_commit();
    };

    issue(0, 0);
    for (int g = 0; g < nch; g++) {
        if (g + 1 < nch) {
            issue(g + 1, (g + 1) & 1);
            asm volatile("cp.async.wait_group 1;" ::: "memory");
        } else {
            asm volatile("cp.async.wait_group 0;" ::: "memory");
        }
        __syncthreads();
        uint32_t sbuf = sbase + (g & 1) * 32768;
        const uint32_t sA = sbuf, sB = sbuf + 16384;
#pragma unroll
        for (int kk = 0; kk < 64; kk += 16) {
            uint32_t af[2][4], bf[4][4];
#pragma unroll
            for (int mi = 0; mi < 2; mi++)
                ldsm_x4(af[mi], sA + sw128((uint32_t)((a_row + mi * 16) * 128 + (kk + a_kof) * 2)));
#pragma unroll
            for (int np = 0; np < 4; np++)
                ldsm_x4(bf[np], sB + sw128((uint32_t)((b_row + np * 16) * 128 + (kk + b_kof) * 2)));
#pragma unroll
            for (int mi = 0; mi < 2; mi++)
#pragma unroll
                for (int ni = 0; ni < 8; ni++)
                    mma_bf16(acc[mi][ni], af[mi],
                             bf[ni >> 1][(ni & 1) * 2], bf[ni >> 1][(ni & 1) * 2 + 1]);
        }
        __syncthreads();
    }

    const int er = lane >> 2, ec = (lane & 3) * 2;
    if (MODE == 1) {
        __nv_bfloat16* C = (__nv_bfloat16*)Cv;
#pragma unroll
        for (int mi = 0; mi < 2; mi++) {
            int row0 = bm + wm + mi * 16 + er;
#pragma unroll
            for (int ni = 0; ni < 8; ni++) {
                int col = bn + wn + ni * 8 + ec;
                __nv_bfloat162 p0 = {__float2bfloat16(acc[mi][ni][0]),
                                     __float2bfloat16(acc[mi][ni][1])};
                __nv_bfloat162 p1 = {__float2bfloat16(acc[mi][ni][2]),
                                     __float2bfloat16(acc[mi][ni][3])};
                *reinterpret_cast<__nv_bfloat162*>(C + (size_t)row0 * N + col)       = p0;
                *reinterpret_cast<__nv_bfloat162*>(C + (size_t)(row0 + 8) * N + col) = p1;
            }
        }
    } else {
        float* C = (float*)Cv;
        if (MODE == 0 && sk == 1) {
#pragma unroll
            for (int mi = 0; mi < 2; mi++) {
                int row0 = bm + wm + mi * 16 + er;
#pragma unroll
                for (int ni = 0; ni < 8; ni++) {
                    int col = bn + wn + ni * 8 + ec;
                    *reinterpret_cast<float2*>(C + (size_t)row0 * N + col) =
                        make_float2(acc[mi][ni][0], acc[mi][ni][1]);
                    *reinterpret_cast<float2*>(C + (size_t)(row0 + 8) * N + col) =
                        make_float2(acc[mi][ni][2], acc[mi][ni][3]);
                }
            }
        } else {
#pragma unroll
            for (int mi = 0; mi < 2; mi++) {
                int row0 = bm + wm + mi * 16 + er;
#pragma unroll
                for (int ni = 0; ni < 8; ni++) {
                    int col = bn + wn + ni * 8 + ec;
                    atomicAdd(C + (size_t)row0 * N + col,       acc[mi][ni][0]);
                    atomicAdd(C + (size_t)row0 * N + col + 1,   acc[mi][ni][1]);
                    atomicAdd(C + (size_t)(row0 + 8) * N + col,     acc[mi][ni][2]);
                    atomicAdd(C + (size_t)(row0 + 8) * N + col + 1, acc[mi][ni][3]);
                }
            }
        }
    }
}

// ==================== sparse aggregation ====================
__global__ void gcn_agg_kernel(const float* __restrict__ xw, const float* __restrict__ bias,
                               float* __restrict__ out, int F, int do_tanh)
{
    int v = blockIdx.x, f = threadIdx.x;
    __shared__ int   sid[256];
    __shared__ float snw[256];
    int nb = d_cnt_in[v], base = d_off_in[v];
    float dv = d_dis_sp[v];
    float acc = 0.f;
    int CH = blockDim.x;
    for (int c0 = 0; c0 < nb; c0 += CH) {
        int m = min(CH, nb - c0);
        __syncthreads();
        if (f < m) {
            int r = d_csc_src[base + c0 + f];
            sid[f] = r;
            snw[f] = d_dis_sp[r];
        }
        __syncthreads();
#pragma unroll 4
        for (int e = 0; e < m; e++)
            acc += snw[e] * xw[(size_t)sid[e] * F + f];
    }
    float o = dv * acc + dv * dv * xw[(size_t)v * F + f] + bias[f];
    out[(size_t)v * F + f] = do_tanh ? tanhf(o) : o;
}

__global__ void gcn_agg_split_kernel(const float* __restrict__ xw, const float* __restrict__ bias,
                                     __nv_bfloat16* __restrict__ hi,
                                     __nv_bfloat16* __restrict__ lo, int F)
{
    int v = blockIdx.x, f = threadIdx.x;
    __shared__ int   sid[256];
    __shared__ float snw[256];
    int nb = d_cnt_in[v], base = d_off_in[v];
    float dv = d_dis_sp[v];
    float acc = 0.f;
    int CH = blockDim.x;
    for (int c0 = 0; c0 < nb; c0 += CH) {
        int m = min(CH, nb - c0);
        __syncthreads();
        if (f < m) {
            int r = d_csc_src[base + c0 + f];
            sid[f] = r;
            snw[f] = d_dis_sp[r];
        }
        __syncthreads();
#pragma unroll 4
        for (int e = 0; e < m; e++)
            acc += snw[e] * xw[(size_t)sid[e] * F + f];
    }
    float o = tanhf(dv * acc + dv * dv * xw[(size_t)v * F + f] + bias[f]);
    __nv_bfloat16 h = __float2bfloat16(o);
    hi[(size_t)v * F + f] = h;
    lo[(size_t)v * F + f] = __float2bfloat16(o - __bfloat162float(h));
}

__global__ void y_agg_split_kernel(const float* __restrict__ x2,
                                   __nv_bfloat16* __restrict__ hi,
                                   __nv_bfloat16* __restrict__ lo)
{
    int v = blockIdx.x, f = threadIdx.x;
    __shared__ int   sid[256];
    __shared__ float snw[256];
    int nb = d_cnt_out[v], base = d_off_out[v];
    float dv = d_dis_dn[v];
    float acc = 0.f;
    for (int c0 = 0; c0 < nb; c0 += 256) {
        int m = min(256, nb - c0);
        __syncthreads();
        if (f < m) {
            int c = d_csr_dst[base + c0 + f];
            sid[f] = c;
            snw[f] = (c == v) ? 0.f : d_dis_dn[c];
        }
        __syncthreads();
#pragma unroll 4
        for (int e = 0; e < m; e++)
            acc += snw[e] * x2[(size_t)sid[e] * HID + f];
    }
    float o = dv * acc + dv * dv * x2[(size_t)v * HID + f];
    __nv_bfloat16 h = __float2bfloat16(o);
    hi[(size_t)v * HID + f] = h;
    lo[(size_t)v * HID + f] = __float2bfloat16(o - __bfloat162float(h));
}

__global__ void t_agg_kernel(const __nv_bfloat16* __restrict__ sh, float* __restrict__ tt)
{
    int v = blockIdx.x, t = threadIdx.x;
    __shared__ int sid[256];
    int nb = d_cnt_out[v], base = d_off_out[v];
    float a0 = 0.f, a1 = 0.f, a2 = 0.f, a3 = 0.f;
    for (int c0 = 0; c0 < nb; c0 += 256) {
        int m = min(256, nb - c0);
        __syncthreads();
        if (t < m) sid[t] = d_csr_dst[base + c0 + t];
        __syncthreads();
#pragma unroll 4
        for (int e = 0; e < m; e++) {
            const __nv_bfloat16* xr = sh + (size_t)sid[e] * KCL;
            __nv_bfloat162 p0 = *reinterpret_cast<const __nv_bfloat162*>(xr + t * 2);
            a0 += __bfloat162float(p0.x);
            a1 += __bfloat162float(p0.y);
            __nv_bfloat162 p1 = *reinterpret_cast<const __nv_bfloat162*>(xr + 512 + t * 2);
            a2 += __bfloat162float(p1.x);
            a3 += __bfloat162float(p1.y);
        }
    }
    tt[(size_t)v * KCL + t * 2]       = a0;
    tt[(size_t)v * KCL + t * 2 + 1]   = a1;
    tt[(size_t)v * KCL + 512 + t * 2]     = a2;
    tt[(size_t)v * KCL + 512 + t * 2 + 1] = a3;
}

__global__ void softmax_ent_kernel(float* __restrict__ s, const float* __restrict__ bp,
                                   __nv_bfloat16* __restrict__ shi,
                                   __nv_bfloat16* __restrict__ slo)
{
    int v = blockIdx.x, t = threadIdx.x;
    float* row = s + (size_t)v * KCL;
    float x0 = row[t]       + bp[t];
    float x1 = row[t + 256] + bp[t + 256];
    float x2 = row[t + 512] + bp[t + 512];
    float x3 = row[t + 768] + bp[t + 768];
    __shared__ float red[256];
    float mx = fmaxf(fmaxf(x0, x1), fmaxf(x2, x3));
    red[t] = mx; __syncthreads();
    for (int o = 128; o > 0; o >>= 1) { if (t < o) red[t] = fmaxf(red[t], red[t + o]); __syncthreads(); }
    float m = red[0]; __syncthreads();
    float e0 = expf(x0 - m), e1 = expf(x1 - m), e2 = expf(x2 - m), e3 = expf(x3 - m);
    red[t] = e0 + e1 + e2 + e3; __syncthreads();
    for (int o = 128; o > 0; o >>= 1) { if (t < o) red[t] += red[t + o]; __syncthreads(); }
    float inv = 1.0f / red[0]; __syncthreads();
    float p0 = e0 * inv, p1 = e1 * inv, p2 = e2 * inv, p3 = e3 * inv;
    row[t] = p0; row[t + 256] = p1; row[t + 512] = p2; row[t + 768] = p3;
    __nv_bfloat16* hrow = shi + (size_t)v * KCL;
    __nv_bfloat16* lrow = slo + (size_t)v * KCL;
    float p[4] = {p0, p1, p2, p3};
#pragma unroll
    for (int q = 0; q < 4; q++) {
        __nv_bfloat16 h = __float2bfloat16(p[q]);
        hrow[t + q * 256] = h;
        lrow[t + q * 256] = __float2bfloat16(p[q] - __bfloat162float(h));
    }
    float ent = -(p0 * logf(p0 + 1e-15f) + p1 * logf(p1 + 1e-15f) +
                  p2 * logf(p2 + 1e-15f) + p3 * logf(p3 + 1e-15f));
    red[t] = ent; __syncthreads();
    for (int o = 128; o > 0; o >>= 1) { if (t < o) red[t] += red[t + o]; __syncthreads(); }
    if (t == 0) atomicAdd(&d_scal[0], (double)red[0]);
}

// merged link-loss reductions
__global__ void linkloss_kernel(const float* __restrict__ t_arr, const float* __restrict__ s_arr,
                                const float* __restrict__ G_arr)
{
    int b = blockIdx.x;
    if (b < 2048) {
        int slot = (b < 1024) ? 1 : 3;
        const float* a = (b < 1024) ? t_arr : G_arr;
        const float* c = (b < 1024) ? s_arr : G_arr;
        int n = (b < 1024) ? N_NODES * KCL : KCL * KCL;
        int lb = (b < 1024) ? b : b - 1024;
        int i = (lb * 256 + threadIdx.x) * 4;
        float p = 0.f;
        int stride = 1024 * 256 * 4;
        for (; i < n; i += stride) {
            float4 va = *reinterpret_cast<const float4*>(a + i);
            float4 vc = *reinterpret_cast<const float4*>(c + i);
            p += va.x * vc.x + va.y * vc.y + va.z * vc.z + va.w * vc.w;
        }
        __shared__ float red[256];
        red[threadIdx.x] = p; __syncthreads();
        for (int o = 128; o > 0; o >>= 1) {
            if (threadIdx.x < o) red[threadIdx.x] += red[threadIdx.x + o];
            __syncthreads();
        }
        if (threadIdx.x == 0) atomicAdd(&d_scal[slot], (double)red[0]);
    } else {
        int v = b - 2048;
        int t = threadIdx.x;
        int nb = d_cnt_out[v], base = d_off_out[v];
        int tot = 0;
        for (int i = t; i < nb; i += blockDim.x) {
            int ci = d_csr_dst[base + i];
            int c = 0;
            for (int j = 0; j < nb; j++) c += (d_csr_dst[base + j] == ci) ? 1 : 0;
            tot += c;
        }
        __shared__ int redi[256];
        redi[t] = tot; __syncthreads();
        for (int o = 128; o > 0; o >>= 1) {
            if (t < o) redi[t] += redi[t + o];
            __syncthreads();
        }
        if (t == 0 && redi[0] != 0) atomicAdd(&d_scal[2], (double)redi[0]);
    }
}

__global__ void finalize_kernel(float* __restrict__ out_link, float* __restrict__ out_ent)
{
    double v = d_scal[2] - 2.0 * d_scal[1] + d_scal[3];
    if (v < 0.0) v = 0.0;
    *out_link = (float)(0.1 * sqrt(v) / ((double)N_NODES * (double)N_NODES));
    *out_ent  = (float)(0.1 * (d_scal[0] / (double)N_NODES));
}

// ==================== host side ====================
static cudaStream_t g_s1, g_s2;
static cudaEvent_t  g_evStart, g_evPrep, g_evFork, g_evJoinD, g_evPair, g_evJoinL;
static int g_init_done = 0;

static void gemm3_s(cudaStream_t st, const __nv_bfloat16* Ah, const __nv_bfloat16* Al,
                    const __nv_bfloat16* Bh, const __nv_bfloat16* Bl,
                    float* C, int M, int N, int K, int SK)
{
    gemm3_mma_kernel<<<dim3(N / 128, M / 128, SK), 256, GEMM3_SMEM_BYTES, st>>>(
        Ah, Al, Bh, Bl, C, M, N, K);
}
static void gemm1_s(cudaStream_t st, const __nv_bfloat16* A, const __nv_bfloat16* B,
                    float* C, int M, int N, int K, int SK)
{
    gemm1_mma_kernel<0><<<dim3(N / 128, M / 128, SK), 256, GEMM1_SMEM_BYTES, st>>>(
        A, B, C, nullptr, nullptr, M, N, K);
}
static void gemm1_bf16_s(cudaStream_t st, const __nv_bfloat16* A, const __nv_bfloat16* B,
                         __nv_bfloat16* C, int M, int N, int K)
{
    gemm1_mma_kernel<1><<<dim3(N / 128, M / 128, 1), 256, GEMM1_SMEM_BYTES, st>>>(
        A, B, C, nullptr, nullptr, M, N, K);
}
static void gemm1_pair_s(cudaStream_t st, const __nv_bfloat16* A,
                         const __nv_bfloat16* B1, float* C1,
                         const __nv_bfloat16* B2, float* C2, int M, int N, int K)
{
    gemm1_mma_kernel<2><<<dim3(N / 128, M / 128, 8), 256, GEMM1_SMEM_BYTES, st>>>(
        A, B1, C1, B2, C2, M, N, K);
}
static void split_s(cudaStream_t st, const float* in, __nv_bfloat16* hi, __nv_bfloat16* lo, int n)
{
    split_kernel<<<(n / 4 + 255) / 256, 256, 0, st>>>(in, hi, lo, n);
}
static void tsplit_s(cudaStream_t st, const float* in, __nv_bfloat16* hi, __nv_bfloat16* lo,
                     int R, int C)
{
    tsplit_kernel<<<dim3(C / 32, R / 32), dim3(32, 8), 0, st>>>(in, hi, lo, R, C);
}

extern "C" void kernel_launch(void* const* d_in, const int* in_sizes, int n_in,
                              void* d_out, int out_size)
{
    if (!g_init_done) {
        cudaFuncSetAttribute(gemm3_mma_kernel, cudaFuncAttributeMaxDynamicSharedMemorySize,
                             GEMM3_SMEM_BYTES);
        cudaFuncSetAttribute(gemm1_mma_kernel<0>, cudaFuncAttributeMaxDynamicSharedMemorySize,
                             GEMM1_SMEM_BYTES);
        cudaFuncSetAttribute(gemm1_mma_kernel<1>, cudaFuncAttributeMaxDynamicSharedMemorySize,
                             GEMM1_SMEM_BYTES);
        cudaFuncSetAttribute(gemm1_mma_kernel<2>, cudaFuncAttributeMaxDynamicSharedMemorySize,
                             GEMM1_SMEM_BYTES);
        cudaStreamCreateWithFlags(&g_s1, cudaStreamNonBlocking);
        cudaStreamCreateWithFlags(&g_s2, cudaStreamNonBlocking);
        cudaEventCreateWithFlags(&g_evStart, cudaEventDisableTiming);
        cudaEventCreateWithFlags(&g_evPrep,  cudaEventDisableTiming);
        cudaEventCreateWithFlags(&g_evFork,  cudaEventDisableTiming);
        cudaEventCreateWithFlags(&g_evJoinD, cudaEventDisableTiming);
        cudaEventCreateWithFlags(&g_evPair,  cudaEventDisableTiming);
        cudaEventCreateWithFlags(&g_evJoinL, cudaEventDisableTiming);
        g_init_done = 1;
    }
    cudaStream_t S0 = 0;         // capture (default) stream
    cudaStream_t S1 = g_s1;      // prep + chain-D stream
    cudaStream_t S2 = g_s2;      // link-loss stream

    const float* nodes = (const float*)d_in[0];
    const int*   ei    = (const int*)d_in[1];
    const float* W1 = (const float*)d_in[3];  const float* b1 = (const float*)d_in[4];
    const float* W2 = (const float*)d_in[5];  const float* b2 = (const float*)d_in[6];
    const float* Wp = (const float*)d_in[7];  const float* bp = (const float*)d_in[8];
    const float* W3 = (const float*)d_in[9];  const float* b3 = (const float*)d_in[10];
    const float* W4 = (const float*)d_in[11]; const float* b4 = (const float*)d_in[12];
    const float* W5 = (const float*)d_in[13]; const float* b5 = (const float*)d_in[14];
    int E = in_sizes[1] / 2;

    float* out      = (float*)d_out;
    float* out_x    = out;
    float* out_adj  = out + (size_t)N_NODES * FEAT;
    float* out_link = out + (size_t)N_NODES * FEAT + (size_t)N_NODES * N_NODES;
    float* out_ent  = out_link + 1;

    float *xwA,*xwB,*xwC,*xwD,*xwE,*x2,*s,*t,*xp,*adjp,*G,*xo;
    cudaGetSymbolAddress((void**)&xwA,  g_xwA);
    cudaGetSymbolAddress((void**)&xwB,  g_xwB);
    cudaGetSymbolAddress((void**)&xwC,  g_xwC);
    cudaGetSymbolAddress((void**)&xwD,  g_xwD);
    cudaGetSymbolAddress((void**)&xwE,  g_xwE);
    cudaGetSymbolAddress((void**)&x2,   g_x2);
    cudaGetSymbolAddress((void**)&s,    g_s);
    cudaGetSymbolAddress((void**)&t,    g_t);
    cudaGetSymbolAddress((void**)&xp,   g_xp);
    cudaGetSymbolAddress((void**)&adjp, g_adjp);
    cudaGetSymbolAddress((void**)&G,    g_G);
    cudaGetSymbolAddress((void**)&xo,   g_xo);

    __nv_bfloat16 *nhi,*nlo,*xhi,*xlo,*shi,*slo,*sthi,*stlo,*x2thi,*x2tlo,*tthi,*ttlo;
    __nv_bfloat16 *xpthi,*xptlo,*apthi,*aptlo,*mbhi;
    __nv_bfloat16 *w1hi,*w1lo,*w2hi,*w2lo,*wphi,*wplo,*w3hi,*w3lo,*w4hi,*w4lo,*w5hi,*w5lo;
    cudaGetSymbolAddress((void**)&nhi,  g_nhi);  cudaGetSymbolAddress((void**)&nlo,  g_nlo);
    cudaGetSymbolAddress((void**)&xhi,  g_xhi);  cudaGetSymbolAddress((void**)&xlo,  g_xlo);
    cudaGetSymbolAddress((void**)&shi,  g_shi);  cudaGetSymbolAddress((void**)&slo,  g_slo);
    cudaGetSymbolAddress((void**)&sthi, g_sthi); cudaGetSymbolAddress((void**)&stlo, g_stlo);
    cudaGetSymbolAddress((void**)&x2thi,g_x2thi);cudaGetSymbolAddress((void**)&x2tlo,g_x2tlo);
    cudaGetSymbolAddress((void**)&tthi, g_tthi); cudaGetSymbolAddress((void**)&ttlo, g_ttlo);
    cudaGetSymbolAddress((void**)&xpthi,g_xpthi);cudaGetSymbolAddress((void**)&xptlo,g_xptlo);
    cudaGetSymbolAddress((void**)&apthi,g_apthi);cudaGetSymbolAddress((void**)&aptlo,g_aptlo);
    cudaGetSymbolAddress((void**)&mbhi, g_mbhi);
    cudaGetSymbolAddress((void**)&w1hi, g_w1hi); cudaGetSymbolAddress((void**)&w1lo, g_w1lo);
    cudaGetSymbolAddress((void**)&w2hi, g_w2hi); cudaGetSymbolAddress((void**)&w2lo, g_w2lo);
    cudaGetSymbolAddress((void**)&wphi, g_wphi); cudaGetSymbolAddress((void**)&wplo, g_wplo);
    cudaGetSymbolAddress((void**)&w3hi, g_w3hi); cudaGetSymbolAddress((void**)&w3lo, g_w3lo);
    cudaGetSymbolAddress((void**)&w4hi, g_w4hi); cudaGetSymbolAddress((void**)&w4lo, g_w4lo);
    cudaGetSymbolAddress((void**)&w5hi, g_w5hi); cudaGetSymbolAddress((void**)&w5lo, g_w5lo);

    // ======== FORK 0: graph prep on S1, dense head on S0 ========
    cudaEventRecord(g_evStart, S0);
    cudaStreamWaitEvent(S1, g_evStart, 0);
    init_zero_kernel<<<(N_NODES + 255) / 256, 256, 0, S1>>>();
    count_kernel<<<(E + 255) / 256, 256, 0, S1>>>(ei, E);
    scan_kernel<<<1, 1024, 0, S1>>>();
    fill_kernel<<<(E + 255) / 256, 256, 0, S1>>>(ei, E);
    cudaEventRecord(g_evPrep, S1);

    // dense head on S0 (independent of graph structure)
    TBatch tb;
    int acc_t = 0;
    auto set_m = [&](int i, const float* src, __nv_bfloat16* hi, __nv_bfloat16* lo, int R, int C) {
        acc_t += (C / 32) * (R / 32);
        tb.m[i] = TMat{src, hi, lo, R, C, acc_t};
    };
    set_m(0, W1, w1hi, w1lo, FEAT, HID);
    set_m(1, W2, w2hi, w2lo, HID, HID);
    set_m(2, Wp, wphi, wplo, HID, KCL);
    set_m(3, W3, w3hi, w3lo, HID, HID);
    set_m(4, W4, w4hi, w4lo, HID, HID);
    set_m(5, W5, w5hi, w5lo, HID, FEAT);
    tsplit_batch_kernel<<<acc_t, dim3(32, 8)>>>(tb);
    zero_all_kernel<<<1024, 256>>>();
    split_s(S0, nodes, nhi, nlo, N_NODES * FEAT);
    gemm3_s(S0, nhi, nlo, w1hi, w1lo, xwA, N_NODES, HID, FEAT, 2);

    // join prep before first CSR/CSC consumer
    cudaStreamWaitEvent(S0, g_evPrep, 0);

    // ---- encoder ----
    gcn_agg_split_kernel<<<N_NODES, HID>>>(xwA, b1, xhi, xlo, HID);
    gemm3_s(S0, xhi, xlo, w2hi, w2lo, xwB, N_NODES, HID, HID, 4);
    gcn_agg_kernel<<<N_NODES, HID>>>(xwB, b2, x2, HID, 1);

    // ---- assignment ----
    y_agg_split_kernel<<<N_NODES, HID>>>(x2, xhi, xlo);
    gemm3_s(S0, xhi, xlo, wphi, wplo, s, N_NODES, KCL, HID, 1);
    softmax_ent_kernel<<<N_NODES, 256>>>(s, bp, shi, slo);

    // shared prerequisites for both chains
    tsplit_s(S0, s, sthi, stlo, N_NODES, KCL);     // S^T
    tsplit_s(S0, x2, x2thi, x2tlo, N_NODES, HID);  // x2^T

    // ======== FORK 1: chain D (xp -> xo -> decoder) on S1 ========
    cudaEventRecord(g_evFork, S0);
    cudaStreamWaitEvent(S1, g_evFork, 0);

    gemm3_s(S1, sthi, stlo, x2thi, x2tlo, xp, KCL, HID, N_NODES, 16);   // xp = S^T x2
    tsplit_s(S1, xp, xpthi, xptlo, KCL, HID);
    gemm3_s(S1, shi, slo, xpthi, xptlo, xo, N_NODES, HID, KCL, 4);      // xo = S xp
    split_s(S1, xo, xhi, xlo, N_NODES * HID);
    gemm3_s(S1, xhi, xlo, w3hi, w3lo, xwC, N_NODES, HID, HID, 4);
    gcn_agg_split_kernel<<<N_NODES, HID, 0, S1>>>(xwC, b3, xhi, xlo, HID);
    gemm3_s(S1, xhi, xlo, w4hi, w4lo, xwD, N_NODES, HID, HID, 4);
    gcn_agg_split_kernel<<<N_NODES, HID, 0, S1>>>(xwD, b4, xhi, xlo, HID);
    gemm3_s(S1, xhi, xlo, w5hi, w5lo, xwE, N_NODES, FEAT, HID, 4);
    gcn_agg_kernel<<<N_NODES, FEAT, 0, S1>>>(xwE, b5, out_x, FEAT, 0);
    cudaEventRecord(g_evJoinD, S1);

    // ======== chain P (adjacency) stays on S0 ========
    t_agg_kernel<<<N_NODES, 256>>>(shi, t);                       // t = A S
    tsplit_s(S0, t, tthi, ttlo, N_NODES, KCL);
    gemm1_pair_s(S0, sthi, tthi, adjp, sthi, G, KCL, KCL, N_NODES);  // adjp & G

    // ======== FORK 2: link-loss reductions on S2 ========
    cudaEventRecord(g_evPair, S0);
    cudaStreamWaitEvent(S2, g_evPair, 0);
    linkloss_kernel<<<6144, 256, 0, S2>>>(t, s, G);
    finalize_kernel<<<1, 1, 0, S2>>>(out_link, out_ent);
    cudaEventRecord(g_evJoinL, S2);

    // chain P continues on S0
    tsplit_s(S0, adjp, apthi, aptlo, KCL, KCL);
    gemm1_bf16_s(S0, shi, apthi, mbhi, N_NODES, KCL, KCL);        // Mb = S adjp
    gemm1_s(S0, mbhi, shi, out_adj, N_NODES, N_NODES, KCL, 1);    // adj_out

    // ======== JOIN ========
    cudaStreamWaitEvent(S0, g_evJoinD, 0);
    cudaStreamWaitEvent(S0, g_evJoinL, 0);
}